// round 4
// baseline (speedup 1.0000x reference)
#include <cuda_runtime.h>
#include <cuda_bf16.h>
#include <cstdint>

#define B_   32
#define D_   256
#define HW_  1024
#define N_   32768
#define K_   1024
#define MARGIN 1e-3f
#define FINF 3.4e38f

static const long long Q_OFF = 8388608LL;   // B*D*H*W

// ---------------- device globals ----------------
__device__ int    g_idx[N_];
__device__ float  g_c2[K_];
__device__ float  g_x2[N_];
__device__ double g_acc;
__device__ __align__(16) __nv_bfloat16 g_xh[(size_t)N_ * D_];
__device__ __align__(16) __nv_bfloat16 g_xl[(size_t)N_ * D_];
__device__ __align__(16) __nv_bfloat16 g_ch[(size_t)K_ * D_];
__device__ __align__(16) __nv_bfloat16 g_cl[(size_t)K_ * D_];
__device__ float g_cv[N_][4];
__device__ int   g_ci[N_][4];

__device__ __forceinline__ uint32_t smem_u32(const void* p) {
    uint32_t a;
    asm("{ .reg .u64 t; cvta.to.shared.u64 t, %1; cvt.u32.u64 %0, t; }"
        : "=r"(a) : "l"(p));
    return a;
}
#define LDSM_X4(r0, r1, r2, r3, addr) \
    asm volatile("ldmatrix.sync.aligned.m8n8.x4.shared.b16 {%0,%1,%2,%3}, [%4];" \
                 : "=r"(r0), "=r"(r1), "=r"(r2), "=r"(r3) : "r"(addr))
#define MMA_BF16(c, a0, a1, a2, a3, b0, b1) \
    asm volatile("mma.sync.aligned.m16n8k16.row.col.f32.bf16.bf16.f32 " \
                 "{%0,%1,%2,%3}, {%4,%5,%6,%7}, {%8,%9}, {%0,%1,%2,%3};" \
                 : "+f"((c)[0]), "+f"((c)[1]), "+f"((c)[2]), "+f"((c)[3]) \
                 : "r"(a0), "r"(a1), "r"(a2), "r"(a3), "r"(b0), "r"(b1))

__device__ __forceinline__ void fold4(float* v, int* ix, float nv, int nk) {
    if (nv < v[3]) {
        if (nv < v[2]) {
            v[3] = v[2]; ix[3] = ix[2];
            if (nv < v[1]) {
                v[2] = v[1]; ix[2] = ix[1];
                if (nv < v[0]) { v[1] = v[0]; ix[1] = ix[0]; v[0] = nv; ix[0] = nk; }
                else           { v[1] = nv; ix[1] = nk; }
            } else { v[2] = nv; ix[2] = nk; }
        } else { v[3] = nv; ix[3] = nk; }
    }
}

// ---------------------------------------------------------------------------
// prep_cb: one block per code. Coalesced bf16 hi/lo split; exact c2
// (sequential no-FMA, replicating XLA:CPU strict-FP scalar reduction).
// ---------------------------------------------------------------------------
__global__ __launch_bounds__(256) void prep_cb(const float* __restrict__ cb) {
    __shared__ float row[256];
    const int k = blockIdx.x, t = threadIdx.x;
    if (k == 0 && t == 0) g_acc = 0.0;
    const float v = cb[(size_t)k * D_ + t];
    row[t] = v;
    const __nv_bfloat16 h = __float2bfloat16(v);
    const __nv_bfloat16 l = __float2bfloat16(__fsub_rn(v, __bfloat162float(h)));
    g_ch[(size_t)k * D_ + t] = h;
    g_cl[(size_t)k * D_ + t] = l;
    __syncthreads();
    if (t == 0) {
        float s = 0.f;
        for (int d = 0; d < D_; ++d)
            s = __fadd_rn(s, __fmul_rn(row[d], row[d]));
        g_c2[k] = s;
    }
}

// ---------------------------------------------------------------------------
// prep_x: transpose (B,D,H,W)->(N,D), exact x2 (sequential no-FMA),
// bf16 hi/lo split. grid 512 x 256, dyn smem 64x257 floats.
// ---------------------------------------------------------------------------
__global__ __launch_bounds__(256) void prep_x(const float* __restrict__ x) {
    extern __shared__ float xs[];   // [64][257]
    const int t   = threadIdx.x;
    const int n0  = blockIdx.x * 64;
    const int b   = n0 >> 10;
    const int hw0 = n0 & 1023;
    const float* xb = x + ((size_t)b << 18) + hw0;

#pragma unroll 8
    for (int i = 0; i < 64; ++i) {
        const int e = t + (i << 8);
        const int d = e >> 6, n = e & 63;
        xs[n * 257 + d] = xb[((size_t)d << 10) + n];
    }
    __syncthreads();

    if (t < 64) {
        const float* r = xs + t * 257;
        float s = 0.f;
        for (int d = 0; d < D_; ++d)
            s = __fadd_rn(s, __fmul_rn(r[d], r[d]));
        g_x2[n0 + t] = s;
    }

#pragma unroll 8
    for (int i = 0; i < 64; ++i) {
        const int e = t + (i << 8);
        const int n = e >> 8, d = e & 255;
        const float v = xs[n * 257 + d];
        const __nv_bfloat16 h = __float2bfloat16(v);
        const __nv_bfloat16 l = __float2bfloat16(__fsub_rn(v, __bfloat162float(h)));
        g_xh[((size_t)(n0 + n) << 8) + d] = h;
        g_xl[((size_t)(n0 + n) << 8) + d] = l;
    }
}

// ---------------------------------------------------------------------------
// gemm_argmin: HMMA (mma.sync m16n8k16 bf16) split GEMM, 3 passes
// (xh*ch + xh*cl + xl*ch) accumulated in fp32 regs, fused top-4 epilogue.
// CTA = 128 rows x all 1024 codes (16 chunks of 64). A hi/lo resident.
// smem pitch 264 bf16 (528B) -> conflict-free ldmatrix.
// ---------------------------------------------------------------------------
#define PITCH 264
#define SA_H   0
#define SA_L   (128 * PITCH * 2)                 // 67584
#define SB_H   (2 * 128 * PITCH * 2)             // 135168
#define SB_L   (SB_H + 64 * PITCH * 2)           // 168960
#define S_C2   (SB_L + 64 * PITCH * 2)           // 202752
#define S_X2   (S_C2 + 4096)                     // 206848
#define S_CV   (S_X2 + 512)                      // 207360
#define S_CI   (S_CV + 8192)                     // 215552
#define GEMM_SMEM (S_CI + 8192)                  // 223744

__global__ __launch_bounds__(256, 1) void gemm_argmin() {
    extern __shared__ char sm[];
    __nv_bfloat16* Ah = (__nv_bfloat16*)(sm + SA_H);
    __nv_bfloat16* Al = (__nv_bfloat16*)(sm + SA_L);
    __nv_bfloat16* Bh = (__nv_bfloat16*)(sm + SB_H);
    __nv_bfloat16* Bl = (__nv_bfloat16*)(sm + SB_L);
    float* c2s = (float*)(sm + S_C2);
    float* x2s = (float*)(sm + S_X2);
    float* cvs = (float*)(sm + S_CV);
    int*   cis = (int*)(sm + S_CI);

    const int t    = threadIdx.x;
    const int w    = t >> 5;
    const int lane = t & 31;
    const int n0   = blockIdx.x * 128;
    const int warpM = w * 16;
    const int g = lane >> 2, q = lane & 3;

    // resident A (hi+lo), c2, x2
#pragma unroll
    for (int i = 0; i < 16; ++i) {
        const int e = t + (i << 8);
        const int row = e >> 5, c8 = (e & 31) << 3;
        const size_t gi = ((size_t)(n0 + row) << 8) + c8;
        *(uint4*)(Ah + row * PITCH + c8) = *(const uint4*)(g_xh + gi);
        *(uint4*)(Al + row * PITCH + c8) = *(const uint4*)(g_xl + gi);
    }
    for (int i = t; i < K_; i += 256) c2s[i] = g_c2[i];
    if (t < 128) x2s[t] = g_x2[n0 + t];

    const uint32_t sb = smem_u32(sm);
    // ldmatrix per-lane base addresses
    const uint32_t a_idx = (uint32_t)((warpM + (lane & 15)) * PITCH + ((lane >> 4) << 3));
    const uint32_t aoh = sb + SA_H + a_idx * 2;
    const uint32_t aol = sb + SA_L + a_idx * 2;
    const uint32_t b_idx = (uint32_t)(((lane & 7) + ((lane >> 4) << 3)) * PITCH
                                      + (((lane >> 3) & 1) << 3));
    const uint32_t boh = sb + SB_H + b_idx * 2;
    const uint32_t bol = sb + SB_L + b_idx * 2;

    float tv[2][4];
    int   ti[2][4];
#pragma unroll
    for (int r = 0; r < 2; ++r)
#pragma unroll
        for (int s = 0; s < 4; ++s) { tv[r][s] = FINF; ti[r][s] = 0; }

    const float x2a = x2s[0];  // placeholder; real read after sync below
    (void)x2a;

    for (int nc = 0; nc < 16; ++nc) {
        __syncthreads();
        // stream B chunk: 64 codes x 256 d, hi+lo
#pragma unroll
        for (int i = 0; i < 8; ++i) {
            const int e = t + (i << 8);
            const int row = e >> 5, c8 = (e & 31) << 3;
            const size_t gi = ((size_t)((nc << 6) + row) << 8) + c8;
            *(uint4*)(Bh + row * PITCH + c8) = *(const uint4*)(g_ch + gi);
            *(uint4*)(Bl + row * PITCH + c8) = *(const uint4*)(g_cl + gi);
        }
        __syncthreads();

        float acc[8][4];
#pragma unroll
        for (int j = 0; j < 8; ++j)
#pragma unroll
            for (int s = 0; s < 4; ++s) acc[j][s] = 0.f;

#pragma unroll 2
        for (int k = 0; k < 16; ++k) {
            uint32_t ah0, ah1, ah2, ah3, al0, al1, al2, al3;
            LDSM_X4(ah0, ah1, ah2, ah3, aoh + k * 32);
            LDSM_X4(al0, al1, al2, al3, aol + k * 32);
#pragma unroll
            for (int p = 0; p < 4; ++p) {
                uint32_t bh0, bh1, bh2, bh3, bl0, bl1, bl2, bl3;
                LDSM_X4(bh0, bh1, bh2, bh3, boh + (p * 16 * PITCH) * 2 + k * 32);
                LDSM_X4(bl0, bl1, bl2, bl3, bol + (p * 16 * PITCH) * 2 + k * 32);
                MMA_BF16(acc[2 * p],     ah0, ah1, ah2, ah3, bh0, bh1);
                MMA_BF16(acc[2 * p + 1], ah0, ah1, ah2, ah3, bh2, bh3);
                MMA_BF16(acc[2 * p],     ah0, ah1, ah2, ah3, bl0, bl1);
                MMA_BF16(acc[2 * p + 1], ah0, ah1, ah2, ah3, bl2, bl3);
                MMA_BF16(acc[2 * p],     al0, al1, al2, al3, bh0, bh1);
                MMA_BF16(acc[2 * p + 1], al0, al1, al2, al3, bh2, bh3);
            }
        }

        // epilogue: fold 32 s-values into per-thread top-4 (2 rows)
        const float x2lo = x2s[warpM + g];
        const float x2hi = x2s[warpM + 8 + g];
#pragma unroll
        for (int j = 0; j < 8; ++j) {
            const int colb = (nc << 6) + (j << 3) + (q << 1);
            const float c2a = c2s[colb], c2b = c2s[colb + 1];
            fold4(tv[0], ti[0], __fadd_rn(__fadd_rn(x2lo, -2.f * acc[j][0]), c2a), colb);
            fold4(tv[0], ti[0], __fadd_rn(__fadd_rn(x2lo, -2.f * acc[j][1]), c2b), colb + 1);
            fold4(tv[1], ti[1], __fadd_rn(__fadd_rn(x2hi, -2.f * acc[j][2]), c2a), colb);
            fold4(tv[1], ti[1], __fadd_rn(__fadd_rn(x2hi, -2.f * acc[j][3]), c2b), colb + 1);
        }
    }

    // per-row merge across the 4 q-lanes: stage to smem, 1 thread per row
    __syncthreads();
#pragma unroll
    for (int s = 0; s < 4; ++s) {
        cvs[((warpM + g) * 4 + q) * 4 + s]     = tv[0][s];
        cis[((warpM + g) * 4 + q) * 4 + s]     = ti[0][s];
        cvs[((warpM + 8 + g) * 4 + q) * 4 + s] = tv[1][s];
        cis[((warpM + 8 + g) * 4 + q) * 4 + s] = ti[1][s];
    }
    __syncthreads();
    if (t < 128) {
        float bv[4] = {FINF, FINF, FINF, FINF};
        int   bi[4] = {0, 0, 0, 0};
#pragma unroll
        for (int qq = 0; qq < 4; ++qq)
#pragma unroll
            for (int s = 0; s < 4; ++s)
                fold4(bv, bi, cvs[(t * 4 + qq) * 4 + s], cis[(t * 4 + qq) * 4 + s]);
        const int n = n0 + t;
#pragma unroll
        for (int s = 0; s < 4; ++s) { g_cv[n][s] = bv[s]; g_ci[n][s] = bi[s]; }
    }
}

// ---------------------------------------------------------------------------
// refine: exact (reference-rounding) winner from candidate set.
// One warp per row.
// ---------------------------------------------------------------------------
__global__ __launch_bounds__(256) void refine_kernel(
    const float* __restrict__ x, const float* __restrict__ cb)
{
    const int n = (blockIdx.x << 3) + (threadIdx.x >> 5);
    const int l = threadIdx.x & 31;

    const float c0 = g_cv[n][0], c1 = g_cv[n][1], c2v = g_cv[n][2], c3 = g_cv[n][3];
    const float lim = c0 + MARGIN;
    const int ncand = 1 + (c1 <= lim) + (c2v <= lim) + (c3 <= lim);

    if (ncand == 1) {
        if (l == 0) g_idx[n] = g_ci[n][0];
        return;
    }

    const int b = n >> 10, hw = n & 1023;
    const float* xp = x + ((size_t)b << 18) + hw;
    const float x2 = g_x2[n];

    float bestv = FINF;
    int   besti = 0x7fffffff;

    if (ncand < 4) {
        if (l < ncand) {
            const int k = g_ci[n][l];
            const float* cr = cb + ((size_t)k << 8);
            float s = 0.f;
#pragma unroll 8
            for (int d = 0; d < D_; ++d)
                s = fmaf(xp[(size_t)d << 10], cr[d], s);
            bestv = __fadd_rn(__fadd_rn(x2, -2.f * s), g_c2[k]);
            besti = k;
        }
    } else {
        for (int k = l; k < K_; k += 32) {
            const float* cr = cb + ((size_t)k << 8);
            float s = 0.f;
#pragma unroll 8
            for (int d = 0; d < D_; ++d)
                s = fmaf(xp[(size_t)d << 10], cr[d], s);
            const float v = __fadd_rn(__fadd_rn(x2, -2.f * s), g_c2[k]);
            if (v < bestv) { bestv = v; besti = k; }
        }
    }
#pragma unroll
    for (int m = 16; m; m >>= 1) {
        const float ov = __shfl_xor_sync(0xffffffffu, bestv, m);
        const int   oi = __shfl_xor_sync(0xffffffffu, besti, m);
        if (ov < bestv || (ov == bestv && oi < besti)) { bestv = ov; besti = oi; }
    }
    if (l == 0) g_idx[n] = besti;
}

// ---------------------------------------------------------------------------
// gather + straight-through output + loss partials + idx-as-float
// ---------------------------------------------------------------------------
__global__ __launch_bounds__(256) void quant_kernel(
    const float* __restrict__ x, const float* __restrict__ cb,
    float* __restrict__ out, long long out_size)
{
    __shared__ float red[256];
    const int t   = threadIdx.x;
    const int n0  = blockIdx.x * 64;
    const int b   = n0 / HW_;
    const int hw0 = n0 % HW_;
    const int tn  = t & 63;
    const int dz  = t >> 6;
    const int n   = n0 + tn;
    const int k   = g_idx[n];

    const float* xb = x   + (size_t)b * D_ * HW_ + hw0 + tn;
    float*       ob = out + (size_t)b * D_ * HW_ + hw0 + tn;
    const float* cr = cb  + (size_t)k * D_;

    float s = 0.f;
#pragma unroll 8
    for (int d = dz; d < D_; d += 4) {
        const float xv   = xb[(size_t)d * HW_];
        const float cv   = cr[d];
        const float diff = __fadd_rn(cv, -xv);
        ob[(size_t)d * HW_] = __fadd_rn(xv, diff);
        s = fmaf(diff, diff, s);
    }

    if (dz == 0 && out_size >= Q_OFF + 3 + N_)
        out[Q_OFF + 3 + n] = (float)k;

    red[t] = s;
    __syncthreads();
    for (int w = 128; w > 0; w >>= 1) {
        if (t < w) red[t] += red[t + w];
        __syncthreads();
    }
    if (t == 0) atomicAdd(&g_acc, (double)red[0]);
}

__global__ void finalize_kernel(float* __restrict__ out, long long out_size) {
    if (out_size >= Q_OFF + 3) {
        const double m = g_acc / (double)((long long)N_ * D_);
        const float  l = (float)m;
        out[Q_OFF + 0] = l;
        out[Q_OFF + 1] = l;
        out[Q_OFF + 2] = __fadd_rn(l, 0.25f * l);
    }
}

// ---------------------------------------------------------------------------
extern "C" void kernel_launch(void* const* d_in, const int* in_sizes, int n_in,
                              void* d_out, int out_size)
{
    const float* x  = (const float*)d_in[0];
    const float* cb = (const float*)d_in[1];
    float*       out = (float*)d_out;
    const long long osz = (long long)out_size;

    cudaFuncSetAttribute(prep_x,
        cudaFuncAttributeMaxDynamicSharedMemorySize, 64 * 257 * 4);
    cudaFuncSetAttribute(gemm_argmin,
        cudaFuncAttributeMaxDynamicSharedMemorySize, GEMM_SMEM);

    prep_cb<<<K_, 256>>>(cb);
    prep_x<<<512, 256, 64 * 257 * 4>>>(x);
    gemm_argmin<<<N_ / 128, 256, GEMM_SMEM>>>();
    refine_kernel<<<N_ / 8, 256>>>(x, cb);
    quant_kernel<<<N_ / 64, 256>>>(x, cb, out, osz);
    finalize_kernel<<<1, 1>>>(out, osz);
}

// round 5
// speedup vs baseline: 1.1309x; 1.1309x over previous
#include <cuda_runtime.h>
#include <cuda_bf16.h>
#include <cstdint>

#define B_   32
#define D_   256
#define HW_  1024
#define N_   32768
#define K_   1024
#define MARGIN 1e-3f
#define FINF 3.4e38f

static const long long Q_OFF = 8388608LL;   // B*D*H*W

// ---------------- device globals ----------------
__device__ int    g_idx[N_];
__device__ float  g_c2[K_];
__device__ float  g_x2[N_];
__device__ double g_acc;
__device__ __align__(16) float         g_xt[(size_t)N_ * D_];   // fp32 transposed x
__device__ __align__(16) __nv_bfloat16 g_xh[(size_t)N_ * D_];
__device__ __align__(16) __nv_bfloat16 g_xl[(size_t)N_ * D_];
__device__ __align__(16) __nv_bfloat16 g_ch[(size_t)K_ * D_];
__device__ __align__(16) __nv_bfloat16 g_cl[(size_t)K_ * D_];
__device__ float g_cv[N_][4];
__device__ int   g_ci[N_][4];

__device__ __forceinline__ uint32_t smem_u32(const void* p) {
    uint32_t a;
    asm("{ .reg .u64 t; cvta.to.shared.u64 t, %1; cvt.u32.u64 %0, t; }"
        : "=r"(a) : "l"(p));
    return a;
}
#define LDSM_X4(r0, r1, r2, r3, addr) \
    asm volatile("ldmatrix.sync.aligned.m8n8.x4.shared.b16 {%0,%1,%2,%3}, [%4];" \
                 : "=r"(r0), "=r"(r1), "=r"(r2), "=r"(r3) : "r"(addr))
#define MMA_BF16(c, a0, a1, a2, a3, b0, b1) \
    asm volatile("mma.sync.aligned.m16n8k16.row.col.f32.bf16.bf16.f32 " \
                 "{%0,%1,%2,%3}, {%4,%5,%6,%7}, {%8,%9}, {%0,%1,%2,%3};" \
                 : "+f"((c)[0]), "+f"((c)[1]), "+f"((c)[2]), "+f"((c)[3]) \
                 : "r"(a0), "r"(a1), "r"(a2), "r"(a3), "r"(b0), "r"(b1))

__device__ __forceinline__ void fold4(float* v, int* ix, float nv, int nk) {
    if (nv < v[3]) {
        if (nv < v[2]) {
            v[3] = v[2]; ix[3] = ix[2];
            if (nv < v[1]) {
                v[2] = v[1]; ix[2] = ix[1];
                if (nv < v[0]) { v[1] = v[0]; ix[1] = ix[0]; v[0] = nv; ix[0] = nk; }
                else           { v[1] = nv; ix[1] = nk; }
            } else { v[2] = nv; ix[2] = nk; }
        } else { v[3] = nv; ix[3] = nk; }
    }
}

// ---------------------------------------------------------------------------
// prep_cb: one block per code. bf16 hi/lo split; exact c2 (sequential no-FMA).
// ---------------------------------------------------------------------------
__global__ __launch_bounds__(256) void prep_cb(const float* __restrict__ cb) {
    __shared__ float row[256];
    const int k = blockIdx.x, t = threadIdx.x;
    if (k == 0 && t == 0) g_acc = 0.0;
    const float v = cb[(size_t)k * D_ + t];
    row[t] = v;
    const __nv_bfloat16 h = __float2bfloat16(v);
    const __nv_bfloat16 l = __float2bfloat16(__fsub_rn(v, __bfloat162float(h)));
    g_ch[(size_t)k * D_ + t] = h;
    g_cl[(size_t)k * D_ + t] = l;
    __syncthreads();
    if (t == 0) {
        float s = 0.f;
        for (int d = 0; d < D_; ++d)
            s = __fadd_rn(s, __fmul_rn(row[d], row[d]));
        g_c2[k] = s;
    }
}

// ---------------------------------------------------------------------------
// prep_x: transpose (B,D,H,W)->(N,D), exact x2 (sequential no-FMA),
// fp32 transposed copy + bf16 hi/lo split.
// ---------------------------------------------------------------------------
__global__ __launch_bounds__(256) void prep_x(const float* __restrict__ x) {
    extern __shared__ float xs[];   // [64][257]
    const int t   = threadIdx.x;
    const int n0  = blockIdx.x * 64;
    const int b   = n0 >> 10;
    const int hw0 = n0 & 1023;
    const float* xb = x + ((size_t)b << 18) + hw0;

#pragma unroll 8
    for (int i = 0; i < 64; ++i) {
        const int e = t + (i << 8);
        const int d = e >> 6, n = e & 63;
        xs[n * 257 + d] = xb[((size_t)d << 10) + n];
    }
    __syncthreads();

    if (t < 64) {
        const float* r = xs + t * 257;
        float s = 0.f;
        for (int d = 0; d < D_; ++d)
            s = __fadd_rn(s, __fmul_rn(r[d], r[d]));
        g_x2[n0 + t] = s;
    }

#pragma unroll 8
    for (int i = 0; i < 64; ++i) {
        const int e = t + (i << 8);
        const int n = e >> 8, d = e & 255;
        const float v = xs[n * 257 + d];
        const __nv_bfloat16 h = __float2bfloat16(v);
        const __nv_bfloat16 l = __float2bfloat16(__fsub_rn(v, __bfloat162float(h)));
        const size_t gi = ((size_t)(n0 + n) << 8) + d;
        g_xt[gi] = v;
        g_xh[gi] = h;
        g_xl[gi] = l;
    }
}

// ---------------------------------------------------------------------------
// gemm_argmin: HMMA bf16 split GEMM (xh*ch + xh*cl + xl*ch), fp32 reg accum,
// fused top-4 epilogue. CTA = 128 rows x 1024 codes (16 chunks of 64).
// ---------------------------------------------------------------------------
#define PITCH 264
#define SA_H   0
#define SA_L   (128 * PITCH * 2)
#define SB_H   (2 * 128 * PITCH * 2)
#define SB_L   (SB_H + 64 * PITCH * 2)
#define S_C2   (SB_L + 64 * PITCH * 2)
#define S_X2   (S_C2 + 4096)
#define S_CV   (S_X2 + 512)
#define S_CI   (S_CV + 8192)
#define GEMM_SMEM (S_CI + 8192)

__global__ __launch_bounds__(256, 1) void gemm_argmin() {
    extern __shared__ char sm[];
    __nv_bfloat16* Ah = (__nv_bfloat16*)(sm + SA_H);
    __nv_bfloat16* Al = (__nv_bfloat16*)(sm + SA_L);
    __nv_bfloat16* Bh = (__nv_bfloat16*)(sm + SB_H);
    __nv_bfloat16* Bl = (__nv_bfloat16*)(sm + SB_L);
    float* c2s = (float*)(sm + S_C2);
    float* x2s = (float*)(sm + S_X2);
    float* cvs = (float*)(sm + S_CV);
    int*   cis = (int*)(sm + S_CI);

    const int t    = threadIdx.x;
    const int w    = t >> 5;
    const int lane = t & 31;
    const int n0   = blockIdx.x * 128;
    const int warpM = w * 16;
    const int g = lane >> 2, q = lane & 3;

#pragma unroll
    for (int i = 0; i < 16; ++i) {
        const int e = t + (i << 8);
        const int row = e >> 5, c8 = (e & 31) << 3;
        const size_t gi = ((size_t)(n0 + row) << 8) + c8;
        *(uint4*)(Ah + row * PITCH + c8) = *(const uint4*)(g_xh + gi);
        *(uint4*)(Al + row * PITCH + c8) = *(const uint4*)(g_xl + gi);
    }
    for (int i = t; i < K_; i += 256) c2s[i] = g_c2[i];
    if (t < 128) x2s[t] = g_x2[n0 + t];

    const uint32_t sb = smem_u32(sm);
    const uint32_t a_idx = (uint32_t)((warpM + (lane & 15)) * PITCH + ((lane >> 4) << 3));
    const uint32_t aoh = sb + SA_H + a_idx * 2;
    const uint32_t aol = sb + SA_L + a_idx * 2;
    const uint32_t b_idx = (uint32_t)(((lane & 7) + ((lane >> 4) << 3)) * PITCH
                                      + (((lane >> 3) & 1) << 3));
    const uint32_t boh = sb + SB_H + b_idx * 2;
    const uint32_t bol = sb + SB_L + b_idx * 2;

    float tv[2][4];
    int   ti[2][4];
#pragma unroll
    for (int r = 0; r < 2; ++r)
#pragma unroll
        for (int s = 0; s < 4; ++s) { tv[r][s] = FINF; ti[r][s] = 0; }

    for (int nc = 0; nc < 16; ++nc) {
        __syncthreads();
#pragma unroll
        for (int i = 0; i < 8; ++i) {
            const int e = t + (i << 8);
            const int row = e >> 5, c8 = (e & 31) << 3;
            const size_t gi = ((size_t)((nc << 6) + row) << 8) + c8;
            *(uint4*)(Bh + row * PITCH + c8) = *(const uint4*)(g_ch + gi);
            *(uint4*)(Bl + row * PITCH + c8) = *(const uint4*)(g_cl + gi);
        }
        __syncthreads();

        float acc[8][4];
#pragma unroll
        for (int j = 0; j < 8; ++j)
#pragma unroll
            for (int s = 0; s < 4; ++s) acc[j][s] = 0.f;

#pragma unroll 2
        for (int k = 0; k < 16; ++k) {
            uint32_t ah0, ah1, ah2, ah3, al0, al1, al2, al3;
            LDSM_X4(ah0, ah1, ah2, ah3, aoh + k * 32);
            LDSM_X4(al0, al1, al2, al3, aol + k * 32);
#pragma unroll
            for (int p = 0; p < 4; ++p) {
                uint32_t bh0, bh1, bh2, bh3, bl0, bl1, bl2, bl3;
                LDSM_X4(bh0, bh1, bh2, bh3, boh + (p * 16 * PITCH) * 2 + k * 32);
                LDSM_X4(bl0, bl1, bl2, bl3, bol + (p * 16 * PITCH) * 2 + k * 32);
                MMA_BF16(acc[2 * p],     ah0, ah1, ah2, ah3, bh0, bh1);
                MMA_BF16(acc[2 * p + 1], ah0, ah1, ah2, ah3, bh2, bh3);
                MMA_BF16(acc[2 * p],     ah0, ah1, ah2, ah3, bl0, bl1);
                MMA_BF16(acc[2 * p + 1], ah0, ah1, ah2, ah3, bl2, bl3);
                MMA_BF16(acc[2 * p],     al0, al1, al2, al3, bh0, bh1);
                MMA_BF16(acc[2 * p + 1], al0, al1, al2, al3, bh2, bh3);
            }
        }

        const float x2lo = x2s[warpM + g];
        const float x2hi = x2s[warpM + 8 + g];
#pragma unroll
        for (int j = 0; j < 8; ++j) {
            const int colb = (nc << 6) + (j << 3) + (q << 1);
            const float c2a = c2s[colb], c2b = c2s[colb + 1];
            fold4(tv[0], ti[0], __fadd_rn(__fadd_rn(x2lo, -2.f * acc[j][0]), c2a), colb);
            fold4(tv[0], ti[0], __fadd_rn(__fadd_rn(x2lo, -2.f * acc[j][1]), c2b), colb + 1);
            fold4(tv[1], ti[1], __fadd_rn(__fadd_rn(x2hi, -2.f * acc[j][2]), c2a), colb);
            fold4(tv[1], ti[1], __fadd_rn(__fadd_rn(x2hi, -2.f * acc[j][3]), c2b), colb + 1);
        }
    }

    __syncthreads();
#pragma unroll
    for (int s = 0; s < 4; ++s) {
        cvs[((warpM + g) * 4 + q) * 4 + s]     = tv[0][s];
        cis[((warpM + g) * 4 + q) * 4 + s]     = ti[0][s];
        cvs[((warpM + 8 + g) * 4 + q) * 4 + s] = tv[1][s];
        cis[((warpM + 8 + g) * 4 + q) * 4 + s] = ti[1][s];
    }
    __syncthreads();
    if (t < 128) {
        float bv[4] = {FINF, FINF, FINF, FINF};
        int   bi[4] = {0, 0, 0, 0};
#pragma unroll
        for (int qq = 0; qq < 4; ++qq)
#pragma unroll
            for (int s = 0; s < 4; ++s)
                fold4(bv, bi, cvs[(t * 4 + qq) * 4 + s], cis[(t * 4 + qq) * 4 + s]);
        const int n = n0 + t;
#pragma unroll
        for (int s = 0; s < 4; ++s) { g_cv[n][s] = bv[s]; g_ci[n][s] = bi[s]; }
    }
}

// ---------------------------------------------------------------------------
// refine: exact winner among margin candidates. Warp per row. All operands
// staged into smem with full-warp MLP before the (irreducible) serial chain.
// ---------------------------------------------------------------------------
__global__ __launch_bounds__(256) void refine_kernel(const float* __restrict__ cb)
{
    __shared__ float sx[8][260];
    __shared__ float sc[8][3][260];
    const int w = threadIdx.x >> 5;
    const int l = threadIdx.x & 31;
    const int n = (blockIdx.x << 3) + w;

    const float v0 = g_cv[n][0], v1 = g_cv[n][1], v2 = g_cv[n][2], v3 = g_cv[n][3];
    const float lim = v0 + MARGIN;
    const int ncand = 1 + (v1 <= lim) + (v2 <= lim) + (v3 <= lim);

    if (ncand == 1) {
        if (l == 0) g_idx[n] = g_ci[n][0];
        return;
    }

    // stage x row (contiguous fp32) into smem: 2 x float4 per lane, coalesced
    {
        const float* xr = g_xt + ((size_t)n << 8);
#pragma unroll
        for (int i = 0; i < 2; ++i) {
            const int d = (l + (i << 5)) << 2;
            *(float4*)&sx[w][d] = *(const float4*)(xr + d);
        }
    }

    const float x2 = g_x2[n];
    float bestv = FINF;
    int   besti = 0x7fffffff;

    if (ncand < 4) {
        // stage candidate codebook rows (contiguous), then 1 chain per lane
        for (int c = 0; c < ncand; ++c) {
            const float* cr = cb + ((size_t)g_ci[n][c] << 8);
#pragma unroll
            for (int i = 0; i < 2; ++i) {
                const int d = (l + (i << 5)) << 2;
                *(float4*)&sc[w][c][d] = *(const float4*)(cr + d);
            }
        }
        __syncwarp();
        if (l < ncand) {
            const int k = g_ci[n][l];
            float s = 0.f;
#pragma unroll 16
            for (int d = 0; d < D_; ++d)
                s = fmaf(sx[w][d], sc[w][l][d], s);
            bestv = __fadd_rn(__fadd_rn(x2, -2.f * s), g_c2[k]);
            besti = k;
        }
    } else {
        // saturated top-4: full exact scan; x from smem, cb contiguous per lane
        __syncwarp();
        for (int k = l; k < K_; k += 32) {
            const float* cr = cb + ((size_t)k << 8);
            float s = 0.f;
#pragma unroll 16
            for (int d = 0; d < D_; ++d)
                s = fmaf(sx[w][d], cr[d], s);
            const float v = __fadd_rn(__fadd_rn(x2, -2.f * s), g_c2[k]);
            if (v < bestv) { bestv = v; besti = k; }   // k ascending per lane
        }
    }
#pragma unroll
    for (int m = 16; m; m >>= 1) {
        const float ov = __shfl_xor_sync(0xffffffffu, bestv, m);
        const int   oi = __shfl_xor_sync(0xffffffffu, besti, m);
        if (ov < bestv || (ov == bestv && oi < besti)) { bestv = ov; besti = oi; }
    }
    if (l == 0) g_idx[n] = besti;
}

// ---------------------------------------------------------------------------
// gather + straight-through output + loss partials + idx-as-float
// ---------------------------------------------------------------------------
__global__ __launch_bounds__(256) void quant_kernel(
    const float* __restrict__ x, const float* __restrict__ cb,
    float* __restrict__ out, long long out_size)
{
    __shared__ float red[256];
    const int t   = threadIdx.x;
    const int n0  = blockIdx.x * 64;
    const int b   = n0 / HW_;
    const int hw0 = n0 % HW_;
    const int tn  = t & 63;
    const int dz  = t >> 6;
    const int n   = n0 + tn;
    const int k   = g_idx[n];

    const float* xb = x   + (size_t)b * D_ * HW_ + hw0 + tn;
    float*       ob = out + (size_t)b * D_ * HW_ + hw0 + tn;
    const float* cr = cb  + (size_t)k * D_;

    float s = 0.f;
#pragma unroll 8
    for (int d = dz; d < D_; d += 4) {
        const float xv   = xb[(size_t)d * HW_];
        const float cv   = cr[d];
        const float diff = __fadd_rn(cv, -xv);
        ob[(size_t)d * HW_] = __fadd_rn(xv, diff);
        s = fmaf(diff, diff, s);
    }

    if (dz == 0 && out_size >= Q_OFF + 3 + N_)
        out[Q_OFF + 3 + n] = (float)k;

    red[t] = s;
    __syncthreads();
    for (int w = 128; w > 0; w >>= 1) {
        if (t < w) red[t] += red[t + w];
        __syncthreads();
    }
    if (t == 0) atomicAdd(&g_acc, (double)red[0]);
}

__global__ void finalize_kernel(float* __restrict__ out, long long out_size) {
    if (out_size >= Q_OFF + 3) {
        const double m = g_acc / (double)((long long)N_ * D_);
        const float  l = (float)m;
        out[Q_OFF + 0] = l;
        out[Q_OFF + 1] = l;
        out[Q_OFF + 2] = __fadd_rn(l, 0.25f * l);
    }
}

// ---------------------------------------------------------------------------
extern "C" void kernel_launch(void* const* d_in, const int* in_sizes, int n_in,
                              void* d_out, int out_size)
{
    const float* x  = (const float*)d_in[0];
    const float* cb = (const float*)d_in[1];
    float*       out = (float*)d_out;
    const long long osz = (long long)out_size;

    cudaFuncSetAttribute(prep_x,
        cudaFuncAttributeMaxDynamicSharedMemorySize, 64 * 257 * 4);
    cudaFuncSetAttribute(gemm_argmin,
        cudaFuncAttributeMaxDynamicSharedMemorySize, GEMM_SMEM);

    prep_cb<<<K_, 256>>>(cb);
    prep_x<<<512, 256, 64 * 257 * 4>>>(x);
    gemm_argmin<<<N_ / 128, 256, GEMM_SMEM>>>();
    refine_kernel<<<N_ / 8, 256>>>(cb);
    quant_kernel<<<N_ / 64, 256>>>(x, cb, out, osz);
    finalize_kernel<<<1, 1>>>(out, osz);
}

// round 6
// speedup vs baseline: 2.0499x; 1.8127x over previous
#include <cuda_runtime.h>
#include <cuda_bf16.h>
#include <cstdint>

#define B_   32
#define D_   256
#define HW_  1024
#define N_   32768
#define K_   1024
#define MARGIN 1e-3f
#define FINF 3.4e38f

static const long long Q_OFF = 8388608LL;   // B*D*H*W

// ---------------- device globals ----------------
__device__ int    g_idx[N_];
__device__ float  g_c2[K_];
__device__ float  g_x2[N_];
__device__ double g_acc;
__device__ __align__(16) float         g_xt[(size_t)N_ * D_];
__device__ __align__(16) __nv_bfloat16 g_xh[(size_t)N_ * D_];
__device__ __align__(16) __nv_bfloat16 g_xl[(size_t)N_ * D_];
__device__ __align__(16) __nv_bfloat16 g_ch[(size_t)K_ * D_];
__device__ __align__(16) __nv_bfloat16 g_cl[(size_t)K_ * D_];
__device__ float g_cv[N_][4];
__device__ int   g_ci[N_][4];
__device__ int   g_qa[N_];
__device__ int   g_qb[N_];
__device__ int   g_qa_n;
__device__ int   g_qb_n;

__device__ __forceinline__ uint32_t smem_u32(const void* p) {
    uint32_t a;
    asm("{ .reg .u64 t; cvta.to.shared.u64 t, %1; cvt.u32.u64 %0, t; }"
        : "=r"(a) : "l"(p));
    return a;
}
#define LDSM_X4(r0, r1, r2, r3, addr) \
    asm volatile("ldmatrix.sync.aligned.m8n8.x4.shared.b16 {%0,%1,%2,%3}, [%4];" \
                 : "=r"(r0), "=r"(r1), "=r"(r2), "=r"(r3) : "r"(addr))
#define MMA_BF16(c, a0, a1, a2, a3, b0, b1) \
    asm volatile("mma.sync.aligned.m16n8k16.row.col.f32.bf16.bf16.f32 " \
                 "{%0,%1,%2,%3}, {%4,%5,%6,%7}, {%8,%9}, {%0,%1,%2,%3};" \
                 : "+f"((c)[0]), "+f"((c)[1]), "+f"((c)[2]), "+f"((c)[3]) \
                 : "r"(a0), "r"(a1), "r"(a2), "r"(a3), "r"(b0), "r"(b1))

__device__ __forceinline__ void fold4(float* v, int* ix, float nv, int nk) {
    if (nv < v[3]) {
        if (nv < v[2]) {
            v[3] = v[2]; ix[3] = ix[2];
            if (nv < v[1]) {
                v[2] = v[1]; ix[2] = ix[1];
                if (nv < v[0]) { v[1] = v[0]; ix[1] = ix[0]; v[0] = nv; ix[0] = nk; }
                else           { v[1] = nv; ix[1] = nk; }
            } else { v[2] = nv; ix[2] = nk; }
        } else { v[3] = nv; ix[3] = nk; }
    }
}

// ---------------------------------------------------------------------------
// prep_cb: bf16 hi/lo split; exact c2 (sequential no-FMA). Resets accumulators.
// ---------------------------------------------------------------------------
__global__ __launch_bounds__(256) void prep_cb(const float* __restrict__ cb) {
    __shared__ float row[256];
    const int k = blockIdx.x, t = threadIdx.x;
    if (k == 0 && t == 0) { g_acc = 0.0; g_qa_n = 0; g_qb_n = 0; }
    const float v = cb[(size_t)k * D_ + t];
    row[t] = v;
    const __nv_bfloat16 h = __float2bfloat16(v);
    const __nv_bfloat16 l = __float2bfloat16(__fsub_rn(v, __bfloat162float(h)));
    g_ch[(size_t)k * D_ + t] = h;
    g_cl[(size_t)k * D_ + t] = l;
    __syncthreads();
    if (t == 0) {
        float s = 0.f;
        for (int d = 0; d < D_; ++d)
            s = __fadd_rn(s, __fmul_rn(row[d], row[d]));
        g_c2[k] = s;
    }
}

// ---------------------------------------------------------------------------
// prep_x: transpose (B,D,H,W)->(N,D), exact x2, fp32 copy + bf16 hi/lo split.
// ---------------------------------------------------------------------------
__global__ __launch_bounds__(256) void prep_x(const float* __restrict__ x) {
    extern __shared__ float xs[];   // [64][257]
    const int t   = threadIdx.x;
    const int n0  = blockIdx.x * 64;
    const int b   = n0 >> 10;
    const int hw0 = n0 & 1023;
    const float* xb = x + ((size_t)b << 18) + hw0;

#pragma unroll 8
    for (int i = 0; i < 64; ++i) {
        const int e = t + (i << 8);
        const int d = e >> 6, n = e & 63;
        xs[n * 257 + d] = xb[((size_t)d << 10) + n];
    }
    __syncthreads();

    if (t < 64) {
        const float* r = xs + t * 257;
        float s = 0.f;
        for (int d = 0; d < D_; ++d)
            s = __fadd_rn(s, __fmul_rn(r[d], r[d]));
        g_x2[n0 + t] = s;
    }

#pragma unroll 8
    for (int i = 0; i < 64; ++i) {
        const int e = t + (i << 8);
        const int n = e >> 8, d = e & 255;
        const float v = xs[n * 257 + d];
        const __nv_bfloat16 h = __float2bfloat16(v);
        const __nv_bfloat16 l = __float2bfloat16(__fsub_rn(v, __bfloat162float(h)));
        const size_t gi = ((size_t)(n0 + n) << 8) + d;
        g_xt[gi] = v;
        g_xh[gi] = h;
        g_xl[gi] = l;
    }
}

// ---------------------------------------------------------------------------
// gemm_argmin: HMMA bf16 split GEMM (xh*ch + xh*cl + xl*ch), fused top-4.
// ---------------------------------------------------------------------------
#define PITCH 264
#define SA_H   0
#define SA_L   (128 * PITCH * 2)
#define SB_H   (2 * 128 * PITCH * 2)
#define SB_L   (SB_H + 64 * PITCH * 2)
#define S_C2   (SB_L + 64 * PITCH * 2)
#define S_X2   (S_C2 + 4096)
#define S_CV   (S_X2 + 512)
#define S_CI   (S_CV + 8192)
#define GEMM_SMEM (S_CI + 8192)

__global__ __launch_bounds__(256, 1) void gemm_argmin() {
    extern __shared__ char sm[];
    __nv_bfloat16* Ah = (__nv_bfloat16*)(sm + SA_H);
    __nv_bfloat16* Al = (__nv_bfloat16*)(sm + SA_L);
    __nv_bfloat16* Bh = (__nv_bfloat16*)(sm + SB_H);
    __nv_bfloat16* Bl = (__nv_bfloat16*)(sm + SB_L);
    float* c2s = (float*)(sm + S_C2);
    float* x2s = (float*)(sm + S_X2);
    float* cvs = (float*)(sm + S_CV);
    int*   cis = (int*)(sm + S_CI);

    const int t    = threadIdx.x;
    const int w    = t >> 5;
    const int lane = t & 31;
    const int n0   = blockIdx.x * 128;
    const int warpM = w * 16;
    const int g = lane >> 2, q = lane & 3;

#pragma unroll
    for (int i = 0; i < 16; ++i) {
        const int e = t + (i << 8);
        const int row = e >> 5, c8 = (e & 31) << 3;
        const size_t gi = ((size_t)(n0 + row) << 8) + c8;
        *(uint4*)(Ah + row * PITCH + c8) = *(const uint4*)(g_xh + gi);
        *(uint4*)(Al + row * PITCH + c8) = *(const uint4*)(g_xl + gi);
    }
    for (int i = t; i < K_; i += 256) c2s[i] = g_c2[i];
    if (t < 128) x2s[t] = g_x2[n0 + t];

    const uint32_t sb = smem_u32(sm);
    const uint32_t a_idx = (uint32_t)((warpM + (lane & 15)) * PITCH + ((lane >> 4) << 3));
    const uint32_t aoh = sb + SA_H + a_idx * 2;
    const uint32_t aol = sb + SA_L + a_idx * 2;
    const uint32_t b_idx = (uint32_t)(((lane & 7) + ((lane >> 4) << 3)) * PITCH
                                      + (((lane >> 3) & 1) << 3));
    const uint32_t boh = sb + SB_H + b_idx * 2;
    const uint32_t bol = sb + SB_L + b_idx * 2;

    float tv[2][4];
    int   ti[2][4];
#pragma unroll
    for (int r = 0; r < 2; ++r)
#pragma unroll
        for (int s = 0; s < 4; ++s) { tv[r][s] = FINF; ti[r][s] = 0; }

    for (int nc = 0; nc < 16; ++nc) {
        __syncthreads();
#pragma unroll
        for (int i = 0; i < 8; ++i) {
            const int e = t + (i << 8);
            const int row = e >> 5, c8 = (e & 31) << 3;
            const size_t gi = ((size_t)((nc << 6) + row) << 8) + c8;
            *(uint4*)(Bh + row * PITCH + c8) = *(const uint4*)(g_ch + gi);
            *(uint4*)(Bl + row * PITCH + c8) = *(const uint4*)(g_cl + gi);
        }
        __syncthreads();

        float acc[8][4];
#pragma unroll
        for (int j = 0; j < 8; ++j)
#pragma unroll
            for (int s = 0; s < 4; ++s) acc[j][s] = 0.f;

#pragma unroll 2
        for (int k = 0; k < 16; ++k) {
            uint32_t ah0, ah1, ah2, ah3, al0, al1, al2, al3;
            LDSM_X4(ah0, ah1, ah2, ah3, aoh + k * 32);
            LDSM_X4(al0, al1, al2, al3, aol + k * 32);
#pragma unroll
            for (int p = 0; p < 4; ++p) {
                uint32_t bh0, bh1, bh2, bh3, bl0, bl1, bl2, bl3;
                LDSM_X4(bh0, bh1, bh2, bh3, boh + (p * 16 * PITCH) * 2 + k * 32);
                LDSM_X4(bl0, bl1, bl2, bl3, bol + (p * 16 * PITCH) * 2 + k * 32);
                MMA_BF16(acc[2 * p],     ah0, ah1, ah2, ah3, bh0, bh1);
                MMA_BF16(acc[2 * p + 1], ah0, ah1, ah2, ah3, bh2, bh3);
                MMA_BF16(acc[2 * p],     ah0, ah1, ah2, ah3, bl0, bl1);
                MMA_BF16(acc[2 * p + 1], ah0, ah1, ah2, ah3, bl2, bl3);
                MMA_BF16(acc[2 * p],     al0, al1, al2, al3, bh0, bh1);
                MMA_BF16(acc[2 * p + 1], al0, al1, al2, al3, bh2, bh3);
            }
        }

        const float x2lo = x2s[warpM + g];
        const float x2hi = x2s[warpM + 8 + g];
#pragma unroll
        for (int j = 0; j < 8; ++j) {
            const int colb = (nc << 6) + (j << 3) + (q << 1);
            const float c2a = c2s[colb], c2b = c2s[colb + 1];
            fold4(tv[0], ti[0], __fadd_rn(__fadd_rn(x2lo, -2.f * acc[j][0]), c2a), colb);
            fold4(tv[0], ti[0], __fadd_rn(__fadd_rn(x2lo, -2.f * acc[j][1]), c2b), colb + 1);
            fold4(tv[1], ti[1], __fadd_rn(__fadd_rn(x2hi, -2.f * acc[j][2]), c2a), colb);
            fold4(tv[1], ti[1], __fadd_rn(__fadd_rn(x2hi, -2.f * acc[j][3]), c2b), colb + 1);
        }
    }

    __syncthreads();
#pragma unroll
    for (int s = 0; s < 4; ++s) {
        cvs[((warpM + g) * 4 + q) * 4 + s]     = tv[0][s];
        cis[((warpM + g) * 4 + q) * 4 + s]     = ti[0][s];
        cvs[((warpM + 8 + g) * 4 + q) * 4 + s] = tv[1][s];
        cis[((warpM + 8 + g) * 4 + q) * 4 + s] = ti[1][s];
    }
    __syncthreads();
    if (t < 128) {
        float bv[4] = {FINF, FINF, FINF, FINF};
        int   bi[4] = {0, 0, 0, 0};
#pragma unroll
        for (int qq = 0; qq < 4; ++qq)
#pragma unroll
            for (int s = 0; s < 4; ++s)
                fold4(bv, bi, cvs[(t * 4 + qq) * 4 + s], cis[(t * 4 + qq) * 4 + s]);
        const int n = n0 + t;
#pragma unroll
        for (int s = 0; s < 4; ++s) { g_cv[n][s] = bv[s]; g_ci[n][s] = bi[s]; }
    }
}

// ---------------------------------------------------------------------------
// classify: resolve unambiguous rows; compact the rest into work queues.
// ---------------------------------------------------------------------------
__global__ __launch_bounds__(256) void classify_kernel() {
    const int n = blockIdx.x * 256 + threadIdx.x;
    const float v0 = g_cv[n][0];
    const float lim = v0 + MARGIN;
    const int ncand = 1 + (g_cv[n][1] <= lim) + (g_cv[n][2] <= lim)
                        + (g_cv[n][3] <= lim);
    if (ncand == 1) {
        g_idx[n] = g_ci[n][0];
    } else if (ncand < 4) {
        g_qa[atomicAdd(&g_qa_n, 1)] = n;
    } else {
        g_qb[atomicAdd(&g_qb_n, 1)] = n;
    }
}

// ---------------------------------------------------------------------------
// refine_small: persistent warps grid-stride over queue A (2-3 candidates).
// Operands staged to smem with coalesced warp loads; <=3 lanes run chains.
// ---------------------------------------------------------------------------
__global__ __launch_bounds__(256) void refine_small(const float* __restrict__ cb)
{
    __shared__ float sx[8][260];
    __shared__ float sc[8][3][260];
    const int w = threadIdx.x >> 5;
    const int l = threadIdx.x & 31;
    const int wi = (blockIdx.x << 3) + w;
    const int stride = gridDim.x << 3;
    const int cnt = g_qa_n;

    for (int i = wi; i < cnt; i += stride) {
        const int n = g_qa[i];
        const float lim = g_cv[n][0] + MARGIN;
        const int ncand = 2 + (g_cv[n][2] <= lim);   // queue A => 2 or 3

        {
            const float* xr = g_xt + ((size_t)n << 8);
#pragma unroll
            for (int ii = 0; ii < 2; ++ii) {
                const int d = (l + (ii << 5)) << 2;
                *(float4*)&sx[w][d] = *(const float4*)(xr + d);
            }
        }
        for (int c = 0; c < ncand; ++c) {
            const float* cr = cb + ((size_t)g_ci[n][c] << 8);
#pragma unroll
            for (int ii = 0; ii < 2; ++ii) {
                const int d = (l + (ii << 5)) << 2;
                *(float4*)&sc[w][c][d] = *(const float4*)(cr + d);
            }
        }
        __syncwarp();

        float bestv = FINF;
        int   besti = 0x7fffffff;
        if (l < ncand) {
            const int k = g_ci[n][l];
            float s = 0.f;
#pragma unroll 16
            for (int d = 0; d < D_; ++d)
                s = fmaf(sx[w][d], sc[w][l][d], s);
            bestv = __fadd_rn(__fadd_rn(g_x2[n], -2.f * s), g_c2[k]);
            besti = k;
        }
#pragma unroll
        for (int m = 16; m; m >>= 1) {
            const float ov = __shfl_xor_sync(0xffffffffu, bestv, m);
            const int   oi = __shfl_xor_sync(0xffffffffu, besti, m);
            if (ov < bestv || (ov == bestv && oi < besti)) { bestv = ov; besti = oi; }
        }
        if (l == 0) g_idx[n] = besti;
        __syncwarp();
    }
}

// ---------------------------------------------------------------------------
// refine_full: block per saturated row. Full exact 1024-code scan with
// codebook staged in 64-code chunks (coalesced), one chain per thread.
// dyn smem: 64*257 floats.
// ---------------------------------------------------------------------------
__global__ __launch_bounds__(256) void refine_full(const float* __restrict__ cb)
{
    extern __shared__ float scf[];          // [64][257]
    __shared__ float sxr[256];
    __shared__ float rv[256];
    __shared__ int   rk[256];
    const int t = threadIdx.x;
    const int cnt = g_qb_n;

    for (int qi = blockIdx.x; qi < cnt; qi += gridDim.x) {
        const int n = g_qb[qi];
        if (t < 64) {
            const float4 v = *(const float4*)(g_xt + ((size_t)n << 8) + (t << 2));
            sxr[(t << 2) + 0] = v.x; sxr[(t << 2) + 1] = v.y;
            sxr[(t << 2) + 2] = v.z; sxr[(t << 2) + 3] = v.w;
        }
        const float x2 = g_x2[n];
        float bestv = FINF;
        int   besti = 0x7fffffff;

        for (int base = 0; base < K_; base += 64) {
            __syncthreads();
            // coalesced stage of 64 codebook rows
#pragma unroll
            for (int i = 0; i < 16; ++i) {
                const int e = t + (i << 8);
                const int row = e >> 6, c4 = (e & 63) << 2;
                const float4 v = *(const float4*)(cb + ((size_t)(base + row) << 8) + c4);
                float* dst = scf + row * 257 + c4;
                dst[0] = v.x; dst[1] = v.y; dst[2] = v.z; dst[3] = v.w;
            }
            __syncthreads();
            if (t < 64) {
                const int k = base + t;
                const float* cr = scf + t * 257;
                float s = 0.f;
#pragma unroll 16
                for (int d = 0; d < D_; ++d)
                    s = fmaf(sxr[d], cr[d], s);
                const float v = __fadd_rn(__fadd_rn(x2, -2.f * s), g_c2[k]);
                if (v < bestv) { bestv = v; besti = k; }  // ascending k per thread
            }
        }
        rv[t] = bestv; rk[t] = besti;
        __syncthreads();
        for (int w = 128; w > 0; w >>= 1) {
            if (t < w) {
                const float ov = rv[t + w]; const int oi = rk[t + w];
                if (ov < rv[t] || (ov == rv[t] && oi < rk[t])) { rv[t] = ov; rk[t] = oi; }
            }
            __syncthreads();
        }
        if (t == 0) g_idx[n] = rk[0];
        __syncthreads();
    }
}

// ---------------------------------------------------------------------------
// gather + straight-through output + loss partials + idx-as-float
// ---------------------------------------------------------------------------
__global__ __launch_bounds__(256) void quant_kernel(
    const float* __restrict__ x, const float* __restrict__ cb,
    float* __restrict__ out, long long out_size)
{
    __shared__ float red[256];
    const int t   = threadIdx.x;
    const int n0  = blockIdx.x * 64;
    const int b   = n0 / HW_;
    const int hw0 = n0 % HW_;
    const int tn  = t & 63;
    const int dz  = t >> 6;
    const int n   = n0 + tn;
    const int k   = g_idx[n];

    const float* xb = x   + (size_t)b * D_ * HW_ + hw0 + tn;
    float*       ob = out + (size_t)b * D_ * HW_ + hw0 + tn;
    const float* cr = cb  + (size_t)k * D_;

    float s = 0.f;
#pragma unroll 8
    for (int d = dz; d < D_; d += 4) {
        const float xv   = xb[(size_t)d * HW_];
        const float cv   = cr[d];
        const float diff = __fadd_rn(cv, -xv);
        ob[(size_t)d * HW_] = __fadd_rn(xv, diff);
        s = fmaf(diff, diff, s);
    }

    if (dz == 0 && out_size >= Q_OFF + 3 + N_)
        out[Q_OFF + 3 + n] = (float)k;

    red[t] = s;
    __syncthreads();
    for (int w = 128; w > 0; w >>= 1) {
        if (t < w) red[t] += red[t + w];
        __syncthreads();
    }
    if (t == 0) atomicAdd(&g_acc, (double)red[0]);
}

__global__ void finalize_kernel(float* __restrict__ out, long long out_size) {
    if (out_size >= Q_OFF + 3) {
        const double m = g_acc / (double)((long long)N_ * D_);
        const float  l = (float)m;
        out[Q_OFF + 0] = l;
        out[Q_OFF + 1] = l;
        out[Q_OFF + 2] = __fadd_rn(l, 0.25f * l);
    }
}

// ---------------------------------------------------------------------------
extern "C" void kernel_launch(void* const* d_in, const int* in_sizes, int n_in,
                              void* d_out, int out_size)
{
    const float* x  = (const float*)d_in[0];
    const float* cb = (const float*)d_in[1];
    float*       out = (float*)d_out;
    const long long osz = (long long)out_size;

    cudaFuncSetAttribute(prep_x,
        cudaFuncAttributeMaxDynamicSharedMemorySize, 64 * 257 * 4);
    cudaFuncSetAttribute(gemm_argmin,
        cudaFuncAttributeMaxDynamicSharedMemorySize, GEMM_SMEM);
    cudaFuncSetAttribute(refine_full,
        cudaFuncAttributeMaxDynamicSharedMemorySize, 64 * 257 * 4);

    prep_cb<<<K_, 256>>>(cb);
    prep_x<<<512, 256, 64 * 257 * 4>>>(x);
    gemm_argmin<<<N_ / 128, 256, GEMM_SMEM>>>();
    classify_kernel<<<N_ / 256, 256>>>();
    refine_small<<<256, 256>>>(cb);
    refine_full<<<64, 256, 64 * 257 * 4>>>(cb);
    quant_kernel<<<N_ / 64, 256>>>(x, cb, out, osz);
    finalize_kernel<<<1, 1>>>(out, osz);
}

// round 7
// speedup vs baseline: 2.0624x; 1.0061x over previous
#include <cuda_runtime.h>
#include <cuda_bf16.h>
#include <cstdint>

#define B_   32
#define D_   256
#define HW_  1024
#define N_   32768
#define K_   1024
#define MARGIN 1e-3f
#define FINF 3.4e38f

static const long long Q_OFF = 8388608LL;   // B*D*H*W

// ---------------- device globals ----------------
__device__ int    g_idx[N_];
__device__ float  g_c2[K_];
__device__ float  g_x2[N_];
__device__ double g_acc;
__device__ __align__(16) float         g_xt[(size_t)N_ * D_];
__device__ __align__(16) __nv_bfloat16 g_xh[(size_t)N_ * D_];
__device__ __align__(16) __nv_bfloat16 g_xl[(size_t)N_ * D_];
__device__ __align__(16) __nv_bfloat16 g_ch[(size_t)K_ * D_];
__device__ __align__(16) __nv_bfloat16 g_cl[(size_t)K_ * D_];
__device__ float g_cv[N_][4];
__device__ int   g_ci[N_][4];
__device__ int   g_qa[N_];
__device__ int   g_qb[N_];
__device__ int   g_qa_n;
__device__ int   g_qb_n;

__device__ __forceinline__ uint32_t smem_u32(const void* p) {
    uint32_t a;
    asm("{ .reg .u64 t; cvta.to.shared.u64 t, %1; cvt.u32.u64 %0, t; }"
        : "=r"(a) : "l"(p));
    return a;
}
#define LDSM_X4(r0, r1, r2, r3, addr) \
    asm volatile("ldmatrix.sync.aligned.m8n8.x4.shared.b16 {%0,%1,%2,%3}, [%4];" \
                 : "=r"(r0), "=r"(r1), "=r"(r2), "=r"(r3) : "r"(addr))
#define MMA_BF16(c, a0, a1, a2, a3, b0, b1) \
    asm volatile("mma.sync.aligned.m16n8k16.row.col.f32.bf16.bf16.f32 " \
                 "{%0,%1,%2,%3}, {%4,%5,%6,%7}, {%8,%9}, {%0,%1,%2,%3};" \
                 : "+f"((c)[0]), "+f"((c)[1]), "+f"((c)[2]), "+f"((c)[3]) \
                 : "r"(a0), "r"(a1), "r"(a2), "r"(a3), "r"(b0), "r"(b1))
#define CP_ASYNC16(dst, src) \
    asm volatile("cp.async.cg.shared.global [%0], [%1], 16;" \
                 :: "r"(dst), "l"(src))
#define CP_COMMIT() asm volatile("cp.async.commit_group;" ::: "memory")
#define CP_WAIT(n)  asm volatile("cp.async.wait_group %0;" :: "n"(n) : "memory")

__device__ __forceinline__ void fold4(float* v, int* ix, float nv, int nk) {
    if (nv < v[3]) {
        if (nv < v[2]) {
            v[3] = v[2]; ix[3] = ix[2];
            if (nv < v[1]) {
                v[2] = v[1]; ix[2] = ix[1];
                if (nv < v[0]) { v[1] = v[0]; ix[1] = ix[0]; v[0] = nv; ix[0] = nk; }
                else           { v[1] = nv; ix[1] = nk; }
            } else { v[2] = nv; ix[2] = nk; }
        } else { v[3] = nv; ix[3] = nk; }
    }
}

// ---------------------------------------------------------------------------
// prep_cb: bf16 hi/lo split; exact c2 (sequential no-FMA). Resets accumulators.
// ---------------------------------------------------------------------------
__global__ __launch_bounds__(256) void prep_cb(const float* __restrict__ cb) {
    __shared__ float row[256];
    const int k = blockIdx.x, t = threadIdx.x;
    if (k == 0 && t == 0) { g_acc = 0.0; g_qa_n = 0; g_qb_n = 0; }
    const float v = cb[(size_t)k * D_ + t];
    row[t] = v;
    const __nv_bfloat16 h = __float2bfloat16(v);
    const __nv_bfloat16 l = __float2bfloat16(__fsub_rn(v, __bfloat162float(h)));
    g_ch[(size_t)k * D_ + t] = h;
    g_cl[(size_t)k * D_ + t] = l;
    __syncthreads();
    if (t == 0) {
        float s = 0.f;
        for (int d = 0; d < D_; ++d)
            s = __fadd_rn(s, __fmul_rn(row[d], row[d]));
        g_c2[k] = s;
    }
}

// ---------------------------------------------------------------------------
// prep_x: transpose (B,D,H,W)->(N,D), exact x2, fp32 copy + bf16 hi/lo split.
// ---------------------------------------------------------------------------
__global__ __launch_bounds__(256) void prep_x(const float* __restrict__ x) {
    extern __shared__ float xs[];   // [64][257]
    const int t   = threadIdx.x;
    const int n0  = blockIdx.x * 64;
    const int b   = n0 >> 10;
    const int hw0 = n0 & 1023;
    const float* xb = x + ((size_t)b << 18) + hw0;

#pragma unroll 8
    for (int i = 0; i < 64; ++i) {
        const int e = t + (i << 8);
        const int d = e >> 6, n = e & 63;
        xs[n * 257 + d] = xb[((size_t)d << 10) + n];
    }
    __syncthreads();

    if (t < 64) {
        const float* r = xs + t * 257;
        float s = 0.f;
        for (int d = 0; d < D_; ++d)
            s = __fadd_rn(s, __fmul_rn(r[d], r[d]));
        g_x2[n0 + t] = s;
    }

#pragma unroll 8
    for (int i = 0; i < 64; ++i) {
        const int e = t + (i << 8);
        const int n = e >> 8, d = e & 255;
        const float v = xs[n * 257 + d];
        const __nv_bfloat16 h = __float2bfloat16(v);
        const __nv_bfloat16 l = __float2bfloat16(__fsub_rn(v, __bfloat162float(h)));
        const size_t gi = ((size_t)(n0 + n) << 8) + d;
        g_xt[gi] = v;
        g_xh[gi] = h;
        g_xl[gi] = l;
    }
}

// ---------------------------------------------------------------------------
// gemm_argmin: HMMA bf16 split GEMM, cp.async double-buffered B (32-code
// chunks), pass-major MMA order, fused top-4 epilogue.
// ---------------------------------------------------------------------------
#define PITCH 264
#define SA_H   0
#define SA_L   (128 * PITCH * 2)                  // 67584
#define SB     (2 * 128 * PITCH * 2)              // 135168
#define SB_STRIDE (32 * PITCH * 2 * 2)            // 33792 per buf (hi+lo)
#define SB_HL  (32 * PITCH * 2)                   // 16896 (lo offset in buf)
#define S_C2   (SB + 2 * SB_STRIDE)               // 202752
#define S_X2   (S_C2 + 4096)
#define S_CV   (S_X2 + 512)
#define S_CI   (S_CV + 8192)
#define GEMM_SMEM (S_CI + 8192)                   // 223744

__device__ __forceinline__ void stage_b(uint32_t sb, int buf, int kc, int t) {
    const uint32_t dst = sb + SB + buf * SB_STRIDE;
#pragma unroll
    for (int i = 0; i < 4; ++i) {
        const int e = t + (i << 8);               // 0..1023
        const int row = e >> 5;                   // 0..31
        const int c8 = (e & 31) << 3;             // 0..248
        const uint32_t doff = (uint32_t)(row * PITCH + c8) * 2;
        const size_t gi = ((size_t)((kc << 5) + row) << 8) + c8;
        CP_ASYNC16(dst + doff, g_ch + gi);
        CP_ASYNC16(dst + SB_HL + doff, g_cl + gi);
    }
}

__global__ __launch_bounds__(256, 1) void gemm_argmin() {
    extern __shared__ char sm[];
    __nv_bfloat16* Ah = (__nv_bfloat16*)(sm + SA_H);
    __nv_bfloat16* Al = (__nv_bfloat16*)(sm + SA_L);
    float* c2s = (float*)(sm + S_C2);
    float* x2s = (float*)(sm + S_X2);
    float* cvs = (float*)(sm + S_CV);
    int*   cis = (int*)(sm + S_CI);

    const int t    = threadIdx.x;
    const int lane = t & 31;
    const int n0   = blockIdx.x * 128;
    const int warpM = (t >> 5) * 16;
    const int g = lane >> 2, q = lane & 3;
    const uint32_t sb = smem_u32(sm);

    // kick off B chunk 0 immediately
    stage_b(sb, 0, 0, t);
    CP_COMMIT();

    // resident A (hi+lo), c2, x2
#pragma unroll
    for (int i = 0; i < 16; ++i) {
        const int e = t + (i << 8);
        const int row = e >> 5, c8 = (e & 31) << 3;
        const size_t gi = ((size_t)(n0 + row) << 8) + c8;
        *(uint4*)(Ah + row * PITCH + c8) = *(const uint4*)(g_xh + gi);
        *(uint4*)(Al + row * PITCH + c8) = *(const uint4*)(g_xl + gi);
    }
    for (int i = t; i < K_; i += 256) c2s[i] = g_c2[i];
    if (t < 128) x2s[t] = g_x2[n0 + t];

    const uint32_t a_idx = (uint32_t)((warpM + (lane & 15)) * PITCH + ((lane >> 4) << 3));
    const uint32_t aoh = sb + SA_H + a_idx * 2;
    const uint32_t aol = sb + SA_L + a_idx * 2;
    const uint32_t b_idx = (uint32_t)(((lane & 7) + ((lane >> 4) << 3)) * PITCH
                                      + (((lane >> 3) & 1) << 3));

    float tv[2][4];
    int   ti[2][4];
#pragma unroll
    for (int r = 0; r < 2; ++r)
#pragma unroll
        for (int s = 0; s < 4; ++s) { tv[r][s] = FINF; ti[r][s] = 0; }

    for (int nc = 0; nc < 32; ++nc) {
        const int buf = nc & 1;
        if (nc < 31) { stage_b(sb, buf ^ 1, nc + 1, t); CP_COMMIT(); }
        if (nc < 31) { CP_WAIT(1); } else { CP_WAIT(0); }
        __syncthreads();

        const uint32_t bh = sb + SB + buf * SB_STRIDE + b_idx * 2;
        const uint32_t bl = bh + SB_HL;

        float acc[4][4];
#pragma unroll
        for (int j = 0; j < 4; ++j)
#pragma unroll
            for (int s = 0; s < 4; ++s) acc[j][s] = 0.f;

#pragma unroll 4
        for (int k = 0; k < 16; ++k) {
            uint32_t ah0, ah1, ah2, ah3, al0, al1, al2, al3;
            uint32_t bh00, bh01, bh02, bh03, bh10, bh11, bh12, bh13;
            uint32_t bl00, bl01, bl02, bl03, bl10, bl11, bl12, bl13;
            LDSM_X4(ah0, ah1, ah2, ah3, aoh + k * 32);
            LDSM_X4(al0, al1, al2, al3, aol + k * 32);
            LDSM_X4(bh00, bh01, bh02, bh03, bh + k * 32);
            LDSM_X4(bh10, bh11, bh12, bh13, bh + 16 * PITCH * 2 + k * 32);
            LDSM_X4(bl00, bl01, bl02, bl03, bl + k * 32);
            LDSM_X4(bl10, bl11, bl12, bl13, bl + 16 * PITCH * 2 + k * 32);
            // pass hh
            MMA_BF16(acc[0], ah0, ah1, ah2, ah3, bh00, bh01);
            MMA_BF16(acc[1], ah0, ah1, ah2, ah3, bh02, bh03);
            MMA_BF16(acc[2], ah0, ah1, ah2, ah3, bh10, bh11);
            MMA_BF16(acc[3], ah0, ah1, ah2, ah3, bh12, bh13);
            // pass hl
            MMA_BF16(acc[0], ah0, ah1, ah2, ah3, bl00, bl01);
            MMA_BF16(acc[1], ah0, ah1, ah2, ah3, bl02, bl03);
            MMA_BF16(acc[2], ah0, ah1, ah2, ah3, bl10, bl11);
            MMA_BF16(acc[3], ah0, ah1, ah2, ah3, bl12, bl13);
            // pass lh
            MMA_BF16(acc[0], al0, al1, al2, al3, bh00, bh01);
            MMA_BF16(acc[1], al0, al1, al2, al3, bh02, bh03);
            MMA_BF16(acc[2], al0, al1, al2, al3, bh10, bh11);
            MMA_BF16(acc[3], al0, al1, al2, al3, bh12, bh13);
        }

        // epilogue: fold this chunk's 32 columns into per-thread top-4
        const float x2lo = x2s[warpM + g];
        const float x2hi = x2s[warpM + 8 + g];
#pragma unroll
        for (int j = 0; j < 4; ++j) {
            const int colb = (nc << 5) + (j << 3) + (q << 1);
            const float c2a = c2s[colb], c2b = c2s[colb + 1];
            fold4(tv[0], ti[0], __fadd_rn(__fadd_rn(x2lo, -2.f * acc[j][0]), c2a), colb);
            fold4(tv[0], ti[0], __fadd_rn(__fadd_rn(x2lo, -2.f * acc[j][1]), c2b), colb + 1);
            fold4(tv[1], ti[1], __fadd_rn(__fadd_rn(x2hi, -2.f * acc[j][2]), c2a), colb);
            fold4(tv[1], ti[1], __fadd_rn(__fadd_rn(x2hi, -2.f * acc[j][3]), c2b), colb + 1);
        }
        __syncthreads();
    }

    // per-row merge across the 4 q-lanes
#pragma unroll
    for (int s = 0; s < 4; ++s) {
        cvs[((warpM + g) * 4 + q) * 4 + s]     = tv[0][s];
        cis[((warpM + g) * 4 + q) * 4 + s]     = ti[0][s];
        cvs[((warpM + 8 + g) * 4 + q) * 4 + s] = tv[1][s];
        cis[((warpM + 8 + g) * 4 + q) * 4 + s] = ti[1][s];
    }
    __syncthreads();
    if (t < 128) {
        float bv[4] = {FINF, FINF, FINF, FINF};
        int   bi[4] = {0, 0, 0, 0};
#pragma unroll
        for (int qq = 0; qq < 4; ++qq)
#pragma unroll
            for (int s = 0; s < 4; ++s)
                fold4(bv, bi, cvs[(t * 4 + qq) * 4 + s], cis[(t * 4 + qq) * 4 + s]);
        const int n = n0 + t;
#pragma unroll
        for (int s = 0; s < 4; ++s) { g_cv[n][s] = bv[s]; g_ci[n][s] = bi[s]; }
    }
}

// ---------------------------------------------------------------------------
// classify: resolve unambiguous rows; compact the rest into work queues.
// ---------------------------------------------------------------------------
__global__ __launch_bounds__(256) void classify_kernel() {
    const int n = blockIdx.x * 256 + threadIdx.x;
    const float lim = g_cv[n][0] + MARGIN;
    const int ncand = 1 + (g_cv[n][1] <= lim) + (g_cv[n][2] <= lim)
                        + (g_cv[n][3] <= lim);
    if (ncand == 1) {
        g_idx[n] = g_ci[n][0];
    } else if (ncand < 4) {
        g_qa[atomicAdd(&g_qa_n, 1)] = n;
    } else {
        g_qb[atomicAdd(&g_qb_n, 1)] = n;
    }
}

// ---------------------------------------------------------------------------
// refine_small: persistent warps grid-stride over queue A (2-3 candidates).
// ---------------------------------------------------------------------------
__global__ __launch_bounds__(256) void refine_small(const float* __restrict__ cb)
{
    __shared__ float sx[8][260];
    __shared__ float sc[8][3][260];
    const int w = threadIdx.x >> 5;
    const int l = threadIdx.x & 31;
    const int wi = (blockIdx.x << 3) + w;
    const int stride = gridDim.x << 3;
    const int cnt = g_qa_n;

    for (int i = wi; i < cnt; i += stride) {
        const int n = g_qa[i];
        const float lim = g_cv[n][0] + MARGIN;
        const int ncand = 2 + (g_cv[n][2] <= lim);

        {
            const float* xr = g_xt + ((size_t)n << 8);
#pragma unroll
            for (int ii = 0; ii < 2; ++ii) {
                const int d = (l + (ii << 5)) << 2;
                *(float4*)&sx[w][d] = *(const float4*)(xr + d);
            }
        }
        for (int c = 0; c < ncand; ++c) {
            const float* cr = cb + ((size_t)g_ci[n][c] << 8);
#pragma unroll
            for (int ii = 0; ii < 2; ++ii) {
                const int d = (l + (ii << 5)) << 2;
                *(float4*)&sc[w][c][d] = *(const float4*)(cr + d);
            }
        }
        __syncwarp();

        float bestv = FINF;
        int   besti = 0x7fffffff;
        if (l < ncand) {
            const int k = g_ci[n][l];
            float s = 0.f;
#pragma unroll 16
            for (int d = 0; d < D_; ++d)
                s = fmaf(sx[w][d], sc[w][l][d], s);
            bestv = __fadd_rn(__fadd_rn(g_x2[n], -2.f * s), g_c2[k]);
            besti = k;
        }
#pragma unroll
        for (int m = 16; m; m >>= 1) {
            const float ov = __shfl_xor_sync(0xffffffffu, bestv, m);
            const int   oi = __shfl_xor_sync(0xffffffffu, besti, m);
            if (ov < bestv || (ov == bestv && oi < besti)) { bestv = ov; besti = oi; }
        }
        if (l == 0) g_idx[n] = besti;
        __syncwarp();
    }
}

// ---------------------------------------------------------------------------
// refine_full: block per saturated row; exact full scan, codebook staged
// in 64-code chunks (coalesced). dyn smem: 64*257 floats.
// ---------------------------------------------------------------------------
__global__ __launch_bounds__(256) void refine_full(const float* __restrict__ cb)
{
    extern __shared__ float scf[];          // [64][257]
    __shared__ float sxr[256];
    __shared__ float rv[256];
    __shared__ int   rk[256];
    const int t = threadIdx.x;
    const int cnt = g_qb_n;

    for (int qi = blockIdx.x; qi < cnt; qi += gridDim.x) {
        const int n = g_qb[qi];
        if (t < 64) {
            const float4 v = *(const float4*)(g_xt + ((size_t)n << 8) + (t << 2));
            sxr[(t << 2) + 0] = v.x; sxr[(t << 2) + 1] = v.y;
            sxr[(t << 2) + 2] = v.z; sxr[(t << 2) + 3] = v.w;
        }
        const float x2 = g_x2[n];
        float bestv = FINF;
        int   besti = 0x7fffffff;

        for (int base = 0; base < K_; base += 64) {
            __syncthreads();
#pragma unroll
            for (int i = 0; i < 16; ++i) {
                const int e = t + (i << 8);
                const int row = e >> 6, c4 = (e & 63) << 2;
                const float4 v = *(const float4*)(cb + ((size_t)(base + row) << 8) + c4);
                float* dst = scf + row * 257 + c4;
                dst[0] = v.x; dst[1] = v.y; dst[2] = v.z; dst[3] = v.w;
            }
            __syncthreads();
            if (t < 64) {
                const int k = base + t;
                const float* cr = scf + t * 257;
                float s = 0.f;
#pragma unroll 16
                for (int d = 0; d < D_; ++d)
                    s = fmaf(sxr[d], cr[d], s);
                const float v = __fadd_rn(__fadd_rn(x2, -2.f * s), g_c2[k]);
                if (v < bestv) { bestv = v; besti = k; }
            }
        }
        rv[t] = bestv; rk[t] = besti;
        __syncthreads();
        for (int w = 128; w > 0; w >>= 1) {
            if (t < w) {
                const float ov = rv[t + w]; const int oi = rk[t + w];
                if (ov < rv[t] || (ov == rv[t] && oi < rk[t])) { rv[t] = ov; rk[t] = oi; }
            }
            __syncthreads();
        }
        if (t == 0) g_idx[n] = rk[0];
        __syncthreads();
    }
}

// ---------------------------------------------------------------------------
// gather + straight-through output + loss partials + idx-as-float
// ---------------------------------------------------------------------------
__global__ __launch_bounds__(256) void quant_kernel(
    const float* __restrict__ x, const float* __restrict__ cb,
    float* __restrict__ out, long long out_size)
{
    __shared__ float red[256];
    const int t   = threadIdx.x;
    const int n0  = blockIdx.x * 64;
    const int b   = n0 / HW_;
    const int hw0 = n0 % HW_;
    const int tn  = t & 63;
    const int dz  = t >> 6;
    const int n   = n0 + tn;
    const int k   = g_idx[n];

    const float* xb = x   + (size_t)b * D_ * HW_ + hw0 + tn;
    float*       ob = out + (size_t)b * D_ * HW_ + hw0 + tn;
    const float* cr = cb  + (size_t)k * D_;

    float s = 0.f;
#pragma unroll 8
    for (int d = dz; d < D_; d += 4) {
        const float xv   = xb[(size_t)d * HW_];
        const float cv   = cr[d];
        const float diff = __fadd_rn(cv, -xv);
        ob[(size_t)d * HW_] = __fadd_rn(xv, diff);
        s = fmaf(diff, diff, s);
    }

    if (dz == 0 && out_size >= Q_OFF + 3 + N_)
        out[Q_OFF + 3 + n] = (float)k;

    red[t] = s;
    __syncthreads();
    for (int w = 128; w > 0; w >>= 1) {
        if (t < w) red[t] += red[t + w];
        __syncthreads();
    }
    if (t == 0) atomicAdd(&g_acc, (double)red[0]);
}

__global__ void finalize_kernel(float* __restrict__ out, long long out_size) {
    if (out_size >= Q_OFF + 3) {
        const double m = g_acc / (double)((long long)N_ * D_);
        const float  l = (float)m;
        out[Q_OFF + 0] = l;
        out[Q_OFF + 1] = l;
        out[Q_OFF + 2] = __fadd_rn(l, 0.25f * l);
    }
}

// ---------------------------------------------------------------------------
extern "C" void kernel_launch(void* const* d_in, const int* in_sizes, int n_in,
                              void* d_out, int out_size)
{
    const float* x  = (const float*)d_in[0];
    const float* cb = (const float*)d_in[1];
    float*       out = (float*)d_out;
    const long long osz = (long long)out_size;

    cudaFuncSetAttribute(prep_x,
        cudaFuncAttributeMaxDynamicSharedMemorySize, 64 * 257 * 4);
    cudaFuncSetAttribute(gemm_argmin,
        cudaFuncAttributeMaxDynamicSharedMemorySize, GEMM_SMEM);
    cudaFuncSetAttribute(refine_full,
        cudaFuncAttributeMaxDynamicSharedMemorySize, 64 * 257 * 4);

    prep_cb<<<K_, 256>>>(cb);
    prep_x<<<512, 256, 64 * 257 * 4>>>(x);
    gemm_argmin<<<N_ / 128, 256, GEMM_SMEM>>>();
    classify_kernel<<<N_ / 256, 256>>>();
    refine_small<<<256, 256>>>(cb);
    refine_full<<<64, 256, 64 * 257 * 4>>>(cb);
    quant_kernel<<<N_ / 64, 256>>>(x, cb, out, osz);
    finalize_kernel<<<1, 1>>>(out, osz);
}

// round 8
// speedup vs baseline: 2.2387x; 1.0855x over previous
#include <cuda_runtime.h>
#include <cuda_bf16.h>
#include <cstdint>

#define B_   32
#define D_   256
#define HW_  1024
#define N_   32768
#define K_   1024
#define MARGIN 1e-3f
#define FINF 3.4e38f

static const long long Q_OFF = 8388608LL;   // B*D*H*W

// ---------------- device globals ----------------
__device__ int    g_idx[N_];
__device__ float  g_c2[K_];
__device__ float  g_x2[N_];
__device__ double g_acc;
__device__ __align__(16) float         g_xt[(size_t)N_ * D_];
__device__ __align__(16) __nv_bfloat16 g_xh[(size_t)N_ * D_];
__device__ __align__(16) __nv_bfloat16 g_ch[(size_t)K_ * D_];
__device__ __align__(16) __nv_bfloat16 g_cl[(size_t)K_ * D_];
__device__ float g_cv[N_][4];
__device__ int   g_ci[N_][4];
__device__ int   g_qa[N_];
__device__ int   g_qb[N_];
__device__ int   g_qa_n;
__device__ int   g_qb_n;

__device__ __forceinline__ uint32_t smem_u32(const void* p) {
    uint32_t a;
    asm("{ .reg .u64 t; cvta.to.shared.u64 t, %1; cvt.u32.u64 %0, t; }"
        : "=r"(a) : "l"(p));
    return a;
}
#define LDSM_X4(r0, r1, r2, r3, addr) \
    asm volatile("ldmatrix.sync.aligned.m8n8.x4.shared.b16 {%0,%1,%2,%3}, [%4];" \
                 : "=r"(r0), "=r"(r1), "=r"(r2), "=r"(r3) : "r"(addr))
#define MMA_BF16(c, a0, a1, a2, a3, b0, b1) \
    asm volatile("mma.sync.aligned.m16n8k16.row.col.f32.bf16.bf16.f32 " \
                 "{%0,%1,%2,%3}, {%4,%5,%6,%7}, {%8,%9}, {%0,%1,%2,%3};" \
                 : "+f"((c)[0]), "+f"((c)[1]), "+f"((c)[2]), "+f"((c)[3]) \
                 : "r"(a0), "r"(a1), "r"(a2), "r"(a3), "r"(b0), "r"(b1))
#define CP_ASYNC16(dst, src) \
    asm volatile("cp.async.cg.shared.global [%0], [%1], 16;" \
                 :: "r"(dst), "l"(src))
#define CP_COMMIT() asm volatile("cp.async.commit_group;" ::: "memory")
#define CP_WAIT(n)  asm volatile("cp.async.wait_group %0;" :: "n"(n) : "memory")

__device__ __forceinline__ void fold4(float* v, int* ix, float nv, int nk) {
    if (nv < v[3]) {
        if (nv < v[2]) {
            v[3] = v[2]; ix[3] = ix[2];
            if (nv < v[1]) {
                v[2] = v[1]; ix[2] = ix[1];
                if (nv < v[0]) { v[1] = v[0]; ix[1] = ix[0]; v[0] = nv; ix[0] = nk; }
                else           { v[1] = nv; ix[1] = nk; }
            } else { v[2] = nv; ix[2] = nk; }
        } else { v[3] = nv; ix[3] = nk; }
    }
}

// ---------------------------------------------------------------------------
__global__ void zero_kernel() { g_acc = 0.0; g_qa_n = 0; g_qb_n = 0; }

// ---------------------------------------------------------------------------
// prep_cb: bf16 hi/lo split; exact c2 (sequential no-FMA).
// ---------------------------------------------------------------------------
__global__ __launch_bounds__(256) void prep_cb(const float* __restrict__ cb) {
    __shared__ float row[256];
    const int k = blockIdx.x, t = threadIdx.x;
    const float v = cb[(size_t)k * D_ + t];
    row[t] = v;
    const __nv_bfloat16 h = __float2bfloat16(v);
    const __nv_bfloat16 l = __float2bfloat16(__fsub_rn(v, __bfloat162float(h)));
    g_ch[(size_t)k * D_ + t] = h;
    g_cl[(size_t)k * D_ + t] = l;
    __syncthreads();
    if (t == 0) {
        float s = 0.f;
        for (int d = 0; d < D_; ++d)
            s = __fadd_rn(s, __fmul_rn(row[d], row[d]));
        g_c2[k] = s;
    }
}

// ---------------------------------------------------------------------------
// prep_x: transpose (B,D,H,W)->(N,D), exact x2, fp32 copy + bf16 hi split.
// ---------------------------------------------------------------------------
__global__ __launch_bounds__(256) void prep_x(const float* __restrict__ x) {
    extern __shared__ float xs[];   // [64][257]
    const int t   = threadIdx.x;
    const int n0  = blockIdx.x * 64;
    const int b   = n0 >> 10;
    const int hw0 = n0 & 1023;
    const float* xb = x + ((size_t)b << 18) + hw0;

#pragma unroll 8
    for (int i = 0; i < 64; ++i) {
        const int e = t + (i << 8);
        const int d = e >> 6, n = e & 63;
        xs[n * 257 + d] = xb[((size_t)d << 10) + n];
    }
    __syncthreads();

    if (t < 64) {
        const float* r = xs + t * 257;
        float s = 0.f;
        for (int d = 0; d < D_; ++d)
            s = __fadd_rn(s, __fmul_rn(r[d], r[d]));
        g_x2[n0 + t] = s;
    }

#pragma unroll 8
    for (int i = 0; i < 64; ++i) {
        const int e = t + (i << 8);
        const int n = e >> 8, d = e & 255;
        const float v = xs[n * 257 + d];
        const size_t gi = ((size_t)(n0 + n) << 8) + d;
        g_xt[gi] = v;
        g_xh[gi] = __float2bfloat16(v);
    }
}

// ---------------------------------------------------------------------------
// gemm_argmin: 2-pass HMMA GEMM  s = xh*ch + xh*cl  (xl*c dropped; error
// ~1.4e-5 sigma << MARGIN/2). A-hi resident; B (hi+lo) 64-code chunks,
// cp.async double-buffered. Fused top-4 epilogue.
// ---------------------------------------------------------------------------
#define PITCH 264
#define SA     0
#define SB     (128 * PITCH * 2)                  // 67584
#define SB_HL  (64 * PITCH * 2)                   // 33792 (lo offset in buf)
#define SB_STRIDE (2 * 64 * PITCH * 2)            // 67584 per buf (hi+lo)
#define S_C2   (SB + 2 * SB_STRIDE)               // 202752
#define S_X2   (S_C2 + 4096)                      // 206848
#define S_CV   (S_X2 + 512)                       // 207360
#define S_CI   (S_CV + 8192)                      // 215552
#define GEMM_SMEM (S_CI + 8192)                   // 223744

__device__ __forceinline__ void stage_b(uint32_t sb, int buf, int kc, int t) {
    const uint32_t dst = sb + SB + buf * SB_STRIDE;
#pragma unroll
    for (int i = 0; i < 8; ++i) {
        const int e = t + (i << 8);               // 0..2047
        const int row = e >> 5;                   // 0..63
        const int c8 = (e & 31) << 3;             // 0..248
        const uint32_t doff = (uint32_t)(row * PITCH + c8) * 2;
        const size_t gi = ((size_t)((kc << 6) + row) << 8) + c8;
        CP_ASYNC16(dst + doff, g_ch + gi);
        CP_ASYNC16(dst + SB_HL + doff, g_cl + gi);
    }
}

__global__ __launch_bounds__(256, 1) void gemm_argmin() {
    extern __shared__ char sm[];
    __nv_bfloat16* Ah = (__nv_bfloat16*)(sm + SA);
    float* c2s = (float*)(sm + S_C2);
    float* x2s = (float*)(sm + S_X2);
    float* cvs = (float*)(sm + S_CV);
    int*   cis = (int*)(sm + S_CI);

    const int t    = threadIdx.x;
    const int lane = t & 31;
    const int n0   = blockIdx.x * 128;
    const int warpM = (t >> 5) * 16;
    const int g = lane >> 2, q = lane & 3;
    const uint32_t sb = smem_u32(sm);

    // kick off B chunk 0 immediately (overlaps the A-resident loads)
    stage_b(sb, 0, 0, t);
    CP_COMMIT();

    // resident A (hi only), c2, x2
#pragma unroll
    for (int i = 0; i < 16; ++i) {
        const int e = t + (i << 8);
        const int row = e >> 5, c8 = (e & 31) << 3;
        *(uint4*)(Ah + row * PITCH + c8) =
            *(const uint4*)(g_xh + ((size_t)(n0 + row) << 8) + c8);
    }
    for (int i = t; i < K_; i += 256) c2s[i] = g_c2[i];
    if (t < 128) x2s[t] = g_x2[n0 + t];

    const uint32_t a_idx = (uint32_t)((warpM + (lane & 15)) * PITCH + ((lane >> 4) << 3));
    const uint32_t aoh = sb + SA + a_idx * 2;
    const uint32_t b_idx = (uint32_t)(((lane & 7) + ((lane >> 4) << 3)) * PITCH
                                      + (((lane >> 3) & 1) << 3));

    float tv[2][4];
    int   ti[2][4];
#pragma unroll
    for (int r = 0; r < 2; ++r)
#pragma unroll
        for (int s = 0; s < 4; ++s) { tv[r][s] = FINF; ti[r][s] = 0; }

    for (int nc = 0; nc < 16; ++nc) {
        const int buf = nc & 1;
        if (nc < 15) { stage_b(sb, buf ^ 1, nc + 1, t); CP_COMMIT(); CP_WAIT(1); }
        else         { CP_WAIT(0); }
        __syncthreads();

        const uint32_t bh = sb + SB + buf * SB_STRIDE + b_idx * 2;
        const uint32_t bl = bh + SB_HL;

        float acc[8][4];
#pragma unroll
        for (int j = 0; j < 8; ++j)
#pragma unroll
            for (int s = 0; s < 4; ++s) acc[j][s] = 0.f;

#pragma unroll 2
        for (int k = 0; k < 16; ++k) {
            uint32_t a0, a1, a2, a3;
            uint32_t fh[4][4], fl[4][4];
            LDSM_X4(a0, a1, a2, a3, aoh + k * 32);
#pragma unroll
            for (int p = 0; p < 4; ++p) {
                LDSM_X4(fh[p][0], fh[p][1], fh[p][2], fh[p][3],
                        bh + (p * 16 * PITCH) * 2 + k * 32);
                LDSM_X4(fl[p][0], fl[p][1], fl[p][2], fl[p][3],
                        bl + (p * 16 * PITCH) * 2 + k * 32);
            }
            // pass hh
#pragma unroll
            for (int p = 0; p < 4; ++p) {
                MMA_BF16(acc[2 * p],     a0, a1, a2, a3, fh[p][0], fh[p][1]);
                MMA_BF16(acc[2 * p + 1], a0, a1, a2, a3, fh[p][2], fh[p][3]);
            }
            // pass hl
#pragma unroll
            for (int p = 0; p < 4; ++p) {
                MMA_BF16(acc[2 * p],     a0, a1, a2, a3, fl[p][0], fl[p][1]);
                MMA_BF16(acc[2 * p + 1], a0, a1, a2, a3, fl[p][2], fl[p][3]);
            }
        }

        // epilogue: fold this chunk's 64 columns into per-thread top-4
        const float x2lo = x2s[warpM + g];
        const float x2hi = x2s[warpM + 8 + g];
#pragma unroll
        for (int j = 0; j < 8; ++j) {
            const int colb = (nc << 6) + (j << 3) + (q << 1);
            const float c2a = c2s[colb], c2b = c2s[colb + 1];
            fold4(tv[0], ti[0], __fadd_rn(__fadd_rn(x2lo, -2.f * acc[j][0]), c2a), colb);
            fold4(tv[0], ti[0], __fadd_rn(__fadd_rn(x2lo, -2.f * acc[j][1]), c2b), colb + 1);
            fold4(tv[1], ti[1], __fadd_rn(__fadd_rn(x2hi, -2.f * acc[j][2]), c2a), colb);
            fold4(tv[1], ti[1], __fadd_rn(__fadd_rn(x2hi, -2.f * acc[j][3]), c2b), colb + 1);
        }
        __syncthreads();
    }

    // per-row merge across the 4 q-lanes
#pragma unroll
    for (int s = 0; s < 4; ++s) {
        cvs[((warpM + g) * 4 + q) * 4 + s]     = tv[0][s];
        cis[((warpM + g) * 4 + q) * 4 + s]     = ti[0][s];
        cvs[((warpM + 8 + g) * 4 + q) * 4 + s] = tv[1][s];
        cis[((warpM + 8 + g) * 4 + q) * 4 + s] = ti[1][s];
    }
    __syncthreads();
    if (t < 128) {
        float bv[4] = {FINF, FINF, FINF, FINF};
        int   bi[4] = {0, 0, 0, 0};
#pragma unroll
        for (int qq = 0; qq < 4; ++qq)
#pragma unroll
            for (int s = 0; s < 4; ++s)
                fold4(bv, bi, cvs[(t * 4 + qq) * 4 + s], cis[(t * 4 + qq) * 4 + s]);
        const int n = n0 + t;
#pragma unroll
        for (int s = 0; s < 4; ++s) { g_cv[n][s] = bv[s]; g_ci[n][s] = bi[s]; }
    }
}

// ---------------------------------------------------------------------------
// classify: resolve unambiguous rows; compact the rest into work queues.
// ---------------------------------------------------------------------------
__global__ __launch_bounds__(256) void classify_kernel() {
    const int n = blockIdx.x * 256 + threadIdx.x;
    const float lim = g_cv[n][0] + MARGIN;
    const int ncand = 1 + (g_cv[n][1] <= lim) + (g_cv[n][2] <= lim)
                        + (g_cv[n][3] <= lim);
    if (ncand == 1) {
        g_idx[n] = g_ci[n][0];
    } else if (ncand < 4) {
        g_qa[atomicAdd(&g_qa_n, 1)] = n;
    } else {
        g_qb[atomicAdd(&g_qb_n, 1)] = n;
    }
}

// ---------------------------------------------------------------------------
// refine_small: persistent warps grid-stride over queue A (2-3 candidates).
// ---------------------------------------------------------------------------
__global__ __launch_bounds__(256) void refine_small(const float* __restrict__ cb)
{
    __shared__ float sx[8][260];
    __shared__ float sc[8][3][260];
    const int w = threadIdx.x >> 5;
    const int l = threadIdx.x & 31;
    const int wi = (blockIdx.x << 3) + w;
    const int stride = gridDim.x << 3;
    const int cnt = g_qa_n;

    for (int i = wi; i < cnt; i += stride) {
        const int n = g_qa[i];
        const float lim = g_cv[n][0] + MARGIN;
        const int ncand = 2 + (g_cv[n][2] <= lim);

        {
            const float* xr = g_xt + ((size_t)n << 8);
#pragma unroll
            for (int ii = 0; ii < 2; ++ii) {
                const int d = (l + (ii << 5)) << 2;
                *(float4*)&sx[w][d] = *(const float4*)(xr + d);
            }
        }
        for (int c = 0; c < ncand; ++c) {
            const float* cr = cb + ((size_t)g_ci[n][c] << 8);
#pragma unroll
            for (int ii = 0; ii < 2; ++ii) {
                const int d = (l + (ii << 5)) << 2;
                *(float4*)&sc[w][c][d] = *(const float4*)(cr + d);
            }
        }
        __syncwarp();

        float bestv = FINF;
        int   besti = 0x7fffffff;
        if (l < ncand) {
            const int k = g_ci[n][l];
            float s = 0.f;
#pragma unroll 16
            for (int d = 0; d < D_; ++d)
                s = fmaf(sx[w][d], sc[w][l][d], s);
            bestv = __fadd_rn(__fadd_rn(g_x2[n], -2.f * s), g_c2[k]);
            besti = k;
        }
#pragma unroll
        for (int m = 16; m; m >>= 1) {
            const float ov = __shfl_xor_sync(0xffffffffu, bestv, m);
            const int   oi = __shfl_xor_sync(0xffffffffu, besti, m);
            if (ov < bestv || (ov == bestv && oi < besti)) { bestv = ov; besti = oi; }
        }
        if (l == 0) g_idx[n] = besti;
        __syncwarp();
    }
}

// ---------------------------------------------------------------------------
// refine_full: block per saturated row; exact full scan, codebook staged
// in 64-code chunks (coalesced). dyn smem: 64*257 floats.
// ---------------------------------------------------------------------------
__global__ __launch_bounds__(256) void refine_full(const float* __restrict__ cb)
{
    extern __shared__ float scf[];          // [64][257]
    __shared__ float sxr[256];
    __shared__ float rv[256];
    __shared__ int   rk[256];
    const int t = threadIdx.x;
    const int cnt = g_qb_n;

    for (int qi = blockIdx.x; qi < cnt; qi += gridDim.x) {
        const int n = g_qb[qi];
        if (t < 64) {
            const float4 v = *(const float4*)(g_xt + ((size_t)n << 8) + (t << 2));
            sxr[(t << 2) + 0] = v.x; sxr[(t << 2) + 1] = v.y;
            sxr[(t << 2) + 2] = v.z; sxr[(t << 2) + 3] = v.w;
        }
        const float x2 = g_x2[n];
        float bestv = FINF;
        int   besti = 0x7fffffff;

        for (int base = 0; base < K_; base += 64) {
            __syncthreads();
#pragma unroll
            for (int i = 0; i < 16; ++i) {
                const int e = t + (i << 8);
                const int row = e >> 6, c4 = (e & 63) << 2;
                const float4 v = *(const float4*)(cb + ((size_t)(base + row) << 8) + c4);
                float* dst = scf + row * 257 + c4;
                dst[0] = v.x; dst[1] = v.y; dst[2] = v.z; dst[3] = v.w;
            }
            __syncthreads();
            if (t < 64) {
                const int k = base + t;
                const float* cr = scf + t * 257;
                float s = 0.f;
#pragma unroll 16
                for (int d = 0; d < D_; ++d)
                    s = fmaf(sxr[d], cr[d], s);
                const float v = __fadd_rn(__fadd_rn(x2, -2.f * s), g_c2[k]);
                if (v < bestv) { bestv = v; besti = k; }
            }
        }
        rv[t] = bestv; rk[t] = besti;
        __syncthreads();
        for (int w = 128; w > 0; w >>= 1) {
            if (t < w) {
                const float ov = rv[t + w]; const int oi = rk[t + w];
                if (ov < rv[t] || (ov == rv[t] && oi < rk[t])) { rv[t] = ov; rk[t] = oi; }
            }
            __syncthreads();
        }
        if (t == 0) g_idx[n] = rk[0];
        __syncthreads();
    }
}

// ---------------------------------------------------------------------------
// gather + straight-through output + loss partials + idx-as-float
// ---------------------------------------------------------------------------
__global__ __launch_bounds__(256) void quant_kernel(
    const float* __restrict__ x, const float* __restrict__ cb,
    float* __restrict__ out, long long out_size)
{
    __shared__ float red[256];
    const int t   = threadIdx.x;
    const int n0  = blockIdx.x * 64;
    const int b   = n0 / HW_;
    const int hw0 = n0 % HW_;
    const int tn  = t & 63;
    const int dz  = t >> 6;
    const int n   = n0 + tn;
    const int k   = g_idx[n];

    const float* xb = x   + (size_t)b * D_ * HW_ + hw0 + tn;
    float*       ob = out + (size_t)b * D_ * HW_ + hw0 + tn;
    const float* cr = cb  + (size_t)k * D_;

    float s = 0.f;
#pragma unroll 8
    for (int d = dz; d < D_; d += 4) {
        const float xv   = xb[(size_t)d * HW_];
        const float cv   = cr[d];
        const float diff = __fadd_rn(cv, -xv);
        ob[(size_t)d * HW_] = __fadd_rn(xv, diff);
        s = fmaf(diff, diff, s);
    }

    if (dz == 0 && out_size >= Q_OFF + 3 + N_)
        out[Q_OFF + 3 + n] = (float)k;

    red[t] = s;
    __syncthreads();
    for (int w = 128; w > 0; w >>= 1) {
        if (t < w) red[t] += red[t + w];
        __syncthreads();
    }
    if (t == 0) atomicAdd(&g_acc, (double)red[0]);
}

__global__ void finalize_kernel(float* __restrict__ out, long long out_size) {
    if (out_size >= Q_OFF + 3) {
        const double m = g_acc / (double)((long long)N_ * D_);
        const float  l = (float)m;
        out[Q_OFF + 0] = l;
        out[Q_OFF + 1] = l;
        out[Q_OFF + 2] = __fadd_rn(l, 0.25f * l);
    }
}

// ---------------------------------------------------------------------------
extern "C" void kernel_launch(void* const* d_in, const int* in_sizes, int n_in,
                              void* d_out, int out_size)
{
    const float* x  = (const float*)d_in[0];
    const float* cb = (const float*)d_in[1];
    float*       out = (float*)d_out;
    const long long osz = (long long)out_size;

    cudaFuncSetAttribute(prep_x,
        cudaFuncAttributeMaxDynamicSharedMemorySize, 64 * 257 * 4);
    cudaFuncSetAttribute(gemm_argmin,
        cudaFuncAttributeMaxDynamicSharedMemorySize, GEMM_SMEM);
    cudaFuncSetAttribute(refine_full,
        cudaFuncAttributeMaxDynamicSharedMemorySize, 64 * 257 * 4);

    zero_kernel<<<1, 1>>>();                       // launch 1
    prep_cb<<<K_, 256>>>(cb);                      // launch 2
    prep_x<<<512, 256, 64 * 257 * 4>>>(x);         // launch 3
    gemm_argmin<<<N_ / 128, 256, GEMM_SMEM>>>();   // launch 4 (ncu target)
    classify_kernel<<<N_ / 256, 256>>>();          // launch 5
    refine_small<<<256, 256>>>(cb);                // launch 6
    refine_full<<<64, 256, 64 * 257 * 4>>>(cb);    // launch 7
    quant_kernel<<<N_ / 64, 256>>>(x, cb, out, osz);
    finalize_kernel<<<1, 1>>>(out, osz);
}